// round 14
// baseline (speedup 1.0000x reference)
#include <cuda_runtime.h>
#include <cuda_fp16.h>
#include <math.h>
#include <stdint.h>

#define S_LEN 1536
#define DM    1024
#define NH    16
#define HD    64
#define H2    32
#define DQK   48
#define DQKP  64
#define KVCC  256
#define ROPE_ 32
#define QCC   384
#define DFF   4096
#define SPP   384
#define EPS_RMS 1.1920929e-07f
#define ATTN_EPS 1e-5f
#define SCALING 0.14433756729740643f
#define LAMBDA_INIT 0.2f

// ------------------------- device scratch -------------------------
__device__ __half g_xin [S_LEN * DM];
__device__ float  g_ckv [S_LEN * 384];
__device__ __half g_ckvn[S_LEN * KVCC];
__device__ __half g_kvup[S_LEN * 2048];
__device__ float  g_cq  [S_LEN * QCC];
__device__ __half g_cqn [S_LEN * QCC];
__device__ __half g_qf  [S_LEN * 1536];
__device__ __half g_Q   [(size_t)H2 * S_LEN * DQKP];
__device__ __half g_K   [(size_t)H2 * S_LEN * DQKP];
__device__ __half g_V   [(size_t)NH * S_LEN * HD];
__device__ __half g_Ph  [(size_t)H2 * S_LEN * S_LEN];   // UNNORMALIZED exp, fp16
__device__ float  g_inv [H2 * S_LEN];                    // per-row 1/sum
__device__ float  g_g   [NH * S_LEN];
__device__ float  g_gp  [12 * NH * S_LEN];               // colmean partials
__device__ float  g_ao  [(size_t)NH * S_LEN * HD];
__device__ __half g_af  [S_LEN * DM];
__device__ float  g_x2  [S_LEN * DM];
__device__ __half g_hb  [S_LEN * DM];
__device__ __half g_act [(size_t)S_LEN * DFF];
__device__ float  g_lambda;
// fp16 weight copies
__device__ __half g_kvdw_h[384 * DM];
__device__ __half g_qdw_h [QCC * DM];
__device__ __half g_kvuw_h[2048 * KVCC];
__device__ __half g_quw_h [1536 * QCC];
__device__ __half g_ow_h  [(size_t)DM * DM];
__device__ __half g_fiw_h [(size_t)2 * DFF * DM];       // swiglu-interleaved rows
__device__ __half g_fow_h [(size_t)DM * DFF];

// ------------------------- helpers -------------------------
__device__ __forceinline__ void cpa16(void* smem_dst, const void* gsrc) {
    unsigned a = (unsigned)__cvta_generic_to_shared(smem_dst);
    asm volatile("cp.async.ca.shared.global [%0], [%1], 16;\n" :: "r"(a), "l"(gsrc));
}
__device__ __forceinline__ void cpa_commit() { asm volatile("cp.async.commit_group;\n"); }
template <int NG>
__device__ __forceinline__ void cpa_wait() { asm volatile("cp.async.wait_group %0;\n" :: "n"(NG)); }

#define LDM_X4(a0,a1,a2,a3,p) \
    asm volatile("ldmatrix.sync.aligned.m8n8.x4.shared.b16 {%0,%1,%2,%3}, [%4];" \
        : "=r"(a0), "=r"(a1), "=r"(a2), "=r"(a3) \
        : "r"((unsigned)__cvta_generic_to_shared(p)))
#define LDM_X2(b0,b1,p) \
    asm volatile("ldmatrix.sync.aligned.m8n8.x2.shared.b16 {%0,%1}, [%2];" \
        : "=r"(b0), "=r"(b1) \
        : "r"((unsigned)__cvta_generic_to_shared(p)))
#define LDM_X2T(b0,b1,p) \
    asm volatile("ldmatrix.sync.aligned.m8n8.x2.trans.shared.b16 {%0,%1}, [%2];" \
        : "=r"(b0), "=r"(b1) \
        : "r"((unsigned)__cvta_generic_to_shared(p)))
#define MMA_F16(d, a, b) \
    asm volatile( \
        "mma.sync.aligned.m16n8k16.row.col.f32.f16.f16.f32 " \
        "{%0,%1,%2,%3}, {%4,%5,%6,%7}, {%8,%9}, {%0,%1,%2,%3};" \
        : "+f"(d[0]), "+f"(d[1]), "+f"(d[2]), "+f"(d[3]) \
        : "r"(a[0]), "r"(a[1]), "r"(a[2]), "r"(a[3]), "r"(b[0]), "r"(b[1]))

#define KSTR 72     /* stride (halves) for 64-wide k-tiles */

// --------- FP16 GEMM: 128xNT tiles (NT=128 or 64), K-tile=64, 2-stage ----------
// MODE: 0 = fp32 out (+Res), 1 = fp16 out, 2 = swiglu fp16 out (paired cols)
#define SMEM_H128 (2 * (128 + 128) * KSTR * 2)
#define SMEM_H64  (2 * (128 + 64)  * KSTR * 2)

template <int MODE, int NT>
__global__ __launch_bounds__(256, 2)
void hgemm(const __half* __restrict__ A, const __half* __restrict__ B,
           const float* __restrict__ Res, void* __restrict__ Cv,
           int M, int N, int K, long long sA, long long sB, long long sC,
           float scale)
{
    constexpr int WN  = NT / 32;          // warps along N: 4 or 2
    constexpr int WMT = (8 / WN) == 2 ? 4 : 2;  // 16-row tiles per warp: 4 or 2
    constexpr int BCH = NT / 32;          // B-tile cp.async chunks per thread

    extern __shared__ __half hsm[];
    __half* AsB = hsm;                    // [2][128*KSTR]
    __half* BsB = hsm + 2 * 128 * KSTR;   // [2][NT*KSTR]

    A += (long long)blockIdx.z * sA;
    B += (long long)blockIdx.z * sB;
    float*  Cf = (float*)Cv  + (long long)blockIdx.z * sC;
    __half* Ch = (__half*)Cv + (long long)blockIdx.z * sC;

    const int tid  = threadIdx.x;
    const int lane = tid & 31;
    const int warp = tid >> 5;
    const int wm   = warp / WN;
    const int wn   = warp % WN;
    const int row0 = blockIdx.y * 128;
    const int col0 = blockIdx.x * NT;
    const int grp  = lane >> 2;
    const int tig  = lane & 3;

    const int nk = K / 64;

    auto load_tiles = [&](int ki, int buf) {
        const __half* Ag = A + (long long)row0 * K + ki * 64;
        __half* Ad = AsB + buf * 128 * KSTR;
#pragma unroll
        for (int it = 0; it < 4; it++) {
            int f = tid + it * 256;
            int r = f >> 3, c8 = (f & 7) * 8;
            cpa16(Ad + r * KSTR + c8, Ag + (long long)r * K + c8);
        }
        const __half* Bg = B + (long long)col0 * K + ki * 64;
        __half* Bd = BsB + buf * NT * KSTR;
#pragma unroll
        for (int it = 0; it < BCH; it++) {
            int f = tid + it * 256;
            int r = f >> 3, c8 = (f & 7) * 8;
            cpa16(Bd + r * KSTR + c8, Bg + (long long)r * K + c8);
        }
        cpa_commit();
    };

    float acc[WMT][4][4];
#pragma unroll
    for (int i = 0; i < WMT; i++)
#pragma unroll
        for (int j = 0; j < 4; j++)
#pragma unroll
            for (int l = 0; l < 4; l++) acc[i][j][l] = 0.f;

    load_tiles(0, 0);

    const int arow = (lane & 15);
    const int asel = (lane >> 4) * 8;
    const int brow = (lane & 7);
    const int bsel = ((lane >> 3) & 1) * 8;

    for (int i = 0; i < nk; i++) {
        int cur = i & 1;
        cpa_wait<0>();
        __syncthreads();
        if (i + 1 < nk) load_tiles(i + 1, cur ^ 1);

        const __half* Ab = AsB + cur * 128 * KSTR;
        const __half* Bb = BsB + cur * NT * KSTR;
#pragma unroll
        for (int kc = 0; kc < 4; kc++) {
            unsigned a[WMT][4], b[4][2];
            int acol = kc * 16 + asel;
            int bcol = kc * 16 + bsel;
#pragma unroll
            for (int mi = 0; mi < WMT; mi++) {
                const __half* p = Ab + (wm * (WMT * 16) + mi * 16 + arow) * KSTR + acol;
                LDM_X4(a[mi][0], a[mi][1], a[mi][2], a[mi][3], p);
            }
#pragma unroll
            for (int ni = 0; ni < 4; ni++) {
                const __half* p = Bb + (wn * 32 + ni * 8 + brow) * KSTR + bcol;
                LDM_X2(b[ni][0], b[ni][1], p);
            }
#pragma unroll
            for (int mi = 0; mi < WMT; mi++)
#pragma unroll
                for (int ni = 0; ni < 4; ni++)
                    MMA_F16(acc[mi][ni], a[mi], b[ni]);
        }
    }

#pragma unroll
    for (int mi = 0; mi < WMT; mi++)
#pragma unroll
        for (int ni = 0; ni < 4; ni++)
#pragma unroll
            for (int h = 0; h < 2; h++) {
                int r = row0 + wm * (WMT * 16) + mi * 16 + grp + h * 8;
                int cc = col0 + wn * 32 + ni * 8 + tig * 2;
                float v0 = acc[mi][ni][h * 2 + 0] * scale;
                float v1 = acc[mi][ni][h * 2 + 1] * scale;
                if (MODE == 2) {
                    float o = v0 * (v1 / (1.f + __expf(-v1)));
                    Ch[(long long)r * DFF + (cc >> 1)] = __float2half_rn(o);
                } else if (MODE == 1) {
                    *(__half2*)(Ch + (long long)r * N + cc) = __floats2half2_rn(v0, v1);
                } else {
                    long long o = (long long)r * N + cc;
                    if (Res) { v0 += Res[o]; v1 += Res[o + 1]; }
                    Cf[o] = v0; Cf[o + 1] = v1;
                }
            }
}

// --------- fused QK^T + masked unnormalized softmax (64-wide j-tiles) ----------
#define QKS 72
#define QK_SMEM (128*QKS*2 + 2*64*QKS*2 + 128*QKS*2)

__global__ __launch_bounds__(256)
void qk_softmax_k(const __half* __restrict__ Q, const __half* __restrict__ Kg,
                  __half* __restrict__ Ph, float* __restrict__ invp)
{
    extern __shared__ char qsm[];
    __half* Qs = (__half*)qsm;            // 128 x QKS
    __half* Ks = Qs + 128 * QKS;          // [2][64 x QKS]
    __half* Os = Ks + 2 * 64 * QKS;       // 128 x QKS staging

    const int h2   = blockIdx.y;
    const int row0 = blockIdx.x * 128;
    const int tid  = threadIdx.x;
    const int lane = tid & 31;
    const int warp = tid >> 5;
    const int grp  = lane >> 2;
    const int tig  = lane & 3;

    const __half* Qh = Q + (long long)h2 * S_LEN * DQKP;
    const __half* Kh = Kg + (long long)h2 * S_LEN * DQKP;
    __half* Pout = Ph + (long long)h2 * S_LEN * S_LEN;

#pragma unroll
    for (int it = 0; it < 4; it++) {
        int f = tid + it * 256, r = f >> 3, c8 = (f & 7) * 8;
        cpa16(Qs + r * QKS + c8, Qh + (long long)(row0 + r) * DQKP + c8);
    }
    cpa_commit();

    auto loadK = [&](int jt, int buf) {
#pragma unroll
        for (int it = 0; it < 2; it++) {
            int f = tid + it * 256, r = f >> 3, c8 = (f & 7) * 8;
            cpa16(Ks + buf * 64 * QKS + r * QKS + c8,
                  Kh + (long long)(jt * 64 + r) * DQKP + c8);
        }
        cpa_commit();
    };

    const int r0  = warp * 16 + grp;
    const int ip0 = (row0 + r0) % SPP;
    const int ip1 = (row0 + r0 + 8) % SPP;

    float s0 = 0.f, s1 = 0.f;

    loadK(0, 0);

    const int NJT = S_LEN / 64;   // 24
    for (int jt = 0; jt < NJT; jt++) {
        int buf = jt & 1;
        if (jt + 1 < NJT) { loadK(jt + 1, buf ^ 1); cpa_wait<1>(); }
        else              { cpa_wait<0>(); }
        __syncthreads();

        float acc[8][4];
#pragma unroll
        for (int ni = 0; ni < 8; ni++)
#pragma unroll
            for (int l = 0; l < 4; l++) acc[ni][l] = 0.f;

        const __half* Kb = Ks + buf * 64 * QKS;
#pragma unroll
        for (int kc = 0; kc < 4; kc++) {
            unsigned a[4];
            const __half* pa = Qs + (warp * 16 + (lane & 15)) * QKS
                                  + kc * 16 + (lane >> 4) * 8;
            LDM_X4(a[0], a[1], a[2], a[3], pa);
#pragma unroll
            for (int ni = 0; ni < 8; ni++) {
                unsigned bb[2];
                const __half* pb = Kb + (ni * 8 + (lane & 7)) * QKS
                                      + kc * 16 + ((lane >> 3) & 1) * 8;
                LDM_X2(bb[0], bb[1], pb);
                MMA_F16(acc[ni], a, bb);
            }
        }

#pragma unroll
        for (int ni = 0; ni < 8; ni++) {
            int c0  = jt * 64 + ni * 8 + tig * 2;
            int jm0 = c0 % SPP;
            float e00 = (jm0     <= ip0) ? __expf(fminf(acc[ni][0] * SCALING, 10.f)) : 0.f;
            float e01 = (jm0 + 1 <= ip0) ? __expf(fminf(acc[ni][1] * SCALING, 10.f)) : 0.f;
            float e10 = (jm0     <= ip1) ? __expf(fminf(acc[ni][2] * SCALING, 10.f)) : 0.f;
            float e11 = (jm0 + 1 <= ip1) ? __expf(fminf(acc[ni][3] * SCALING, 10.f)) : 0.f;
            s0 += e00 + e01;
            s1 += e10 + e11;
            *(__half2*)(Os + r0 * QKS + ni * 8 + tig * 2)       = __floats2half2_rn(e00, e01);
            *(__half2*)(Os + (r0 + 8) * QKS + ni * 8 + tig * 2) = __floats2half2_rn(e10, e11);
        }
        __syncthreads();

#pragma unroll
        for (int it = 0; it < 4; it++) {
            int f = tid + it * 256, r = f >> 3, c8 = (f & 7) * 8;
            uint4 u = *(uint4*)(Os + r * QKS + c8);
            *(uint4*)(Pout + (long long)(row0 + r) * S_LEN + jt * 64 + c8) = u;
        }
        __syncthreads();
    }

#pragma unroll
    for (int x = 1; x <= 2; x <<= 1) {
        s0 += __shfl_xor_sync(0xffffffffu, s0, x);
        s1 += __shfl_xor_sync(0xffffffffu, s1, x);
    }
    if (tig == 0) {
        invp[h2 * S_LEN + row0 + r0]     = 1.f / s0;
        invp[h2 * S_LEN + row0 + r0 + 8] = 1.f / s1;
    }
}

// --------------- fused differential-combine + AV GEMM, K-tile 64 ---------------
#define AVM 64

__global__ __launch_bounds__(256)
void av_k(const __half* __restrict__ Ph, const float* __restrict__ invp,
          const __half* __restrict__ V,
          const float* __restrict__ g, const float* __restrict__ lamp,
          float* __restrict__ O)
{
    __shared__ __half As[AVM * KSTR];
    __shared__ __half Bs[64 * KSTR];
    __shared__ float  sI1[AVM], sI2[AVM];

    const int h    = blockIdx.y;
    const int row0 = blockIdx.x * AVM;
    const int tid  = threadIdx.x;
    const int lane = tid & 31;
    const int warp = tid >> 5;
    const int wm   = warp >> 1;
    const int wn   = warp & 1;
    const int grp  = lane >> 2;
    const int tig  = lane & 3;

    const float lam = *lamp;
    const float gl  = lam * (1.f / (float)S_LEN);
    const __half* p1 = Ph + (long long)(2 * h) * S_LEN * S_LEN;
    const __half* p2 = Ph + (long long)(2 * h + 1) * S_LEN * S_LEN;
    const __half* Vh = V + (long long)h * S_LEN * HD;
    const float*  gh = g + h * S_LEN;

    if (tid < AVM) {
        sI1[tid] = invp[(2 * h) * S_LEN + row0 + tid];
        sI2[tid] = invp[(2 * h + 1) * S_LEN + row0 + tid];
    }
    __syncthreads();

    float acc[4][4];
#pragma unroll
    for (int j = 0; j < 4; j++)
#pragma unroll
        for (int l = 0; l < 4; l++) acc[j][l] = 0.f;

    for (int j0 = 0; j0 < S_LEN; j0 += 64) {
#pragma unroll
        for (int it = 0; it < 2; it++) {
            int f = tid + it * 256;
            int kk = f >> 3, c8 = (f & 7) * 8;
            cpa16(Bs + kk * KSTR + c8, Vh + (long long)(j0 + kk) * HD + c8);
        }
        cpa_commit();

#pragma unroll
        for (int it = 0; it < 2; it++) {
            int f = tid + it * 256;
            int r = f >> 3, c8 = (f & 7) * 8;
            int ip = (row0 + r) % SPP;
            float i1 = sI1[r], i2 = sI2[r];
            long long off = (long long)(row0 + r) * S_LEN + j0 + c8;
            uint4 u1 = *(const uint4*)(p1 + off);
            uint4 u2 = *(const uint4*)(p2 + off);
            const __half2* h1 = (const __half2*)&u1;
            const __half2* h2 = (const __half2*)&u2;
            __half outh[8];
            int jb = j0 + c8;
#pragma unroll
            for (int e = 0; e < 4; e++) {
                float2 f1 = __half22float2(h1[e]);
                float2 f2 = __half22float2(h2[e]);
                int ja = jb + 2 * e, jbb = ja + 1;
                float o0 = ((ja  % SPP) > ip) ? 0.f
                           : (f1.x * i1 - lam * (f2.x * i2) + gl * gh[ja]);
                float o1 = ((jbb % SPP) > ip) ? 0.f
                           : (f1.y * i1 - lam * (f2.y * i2) + gl * gh[jbb]);
                outh[2 * e]     = __float2half_rn(o0);
                outh[2 * e + 1] = __float2half_rn(o1);
            }
            *(uint4*)(As + r * KSTR + c8) = *(uint4*)outh;
        }
        cpa_wait<0>();
        __syncthreads();

#pragma unroll
        for (int kc = 0; kc < 4; kc++) {
            unsigned a[4], b[4][2];
            {
                const __half* p = As + (wm * 16 + (lane & 15)) * KSTR
                                     + kc * 16 + (lane >> 4) * 8;
                LDM_X4(a[0], a[1], a[2], a[3], p);
            }
#pragma unroll
            for (int ni = 0; ni < 4; ni++) {
                int krow = kc * 16 + ((lane >> 3) & 1) * 8 + (lane & 7);
                int ncol = wn * 32 + ni * 8;
                const __half* p = Bs + krow * KSTR + ncol;
                LDM_X2T(b[ni][0], b[ni][1], p);
            }
#pragma unroll
            for (int ni = 0; ni < 4; ni++)
                MMA_F16(acc[ni], a, b[ni]);
        }
        __syncthreads();
    }

#pragma unroll
    for (int ni = 0; ni < 4; ni++)
#pragma unroll
        for (int hh = 0; hh < 2; hh++) {
            int r = row0 + wm * 16 + grp + hh * 8;
            int cc = wn * 32 + ni * 8 + tig * 2;
            long long o = ((long long)h * S_LEN + r) * HD + cc;
            O[o]     = acc[ni][hh * 2 + 0];
            O[o + 1] = acc[ni][hh * 2 + 1];
        }
}

// ------------------------- rmsnorm: fp32 in -> fp16 out -------------------------
__global__ void rmsnorm_h(const float* __restrict__ in, const float* __restrict__ w,
                          __half* __restrict__ out, int cols, int in_ld, int out_ld,
                          float eps)
{
    const long long row = blockIdx.x;
    const float* ip = in + row * in_ld;
    __half* op = out + row * out_ld;

    float ss = 0.f;
    for (int j = threadIdx.x; j < cols; j += blockDim.x) {
        float v = ip[j];
        ss += v * v;
    }
    __shared__ float sh[32];
    int lane = threadIdx.x & 31, wid = threadIdx.x >> 5;
#pragma unroll
    for (int o = 16; o; o >>= 1) ss += __shfl_xor_sync(0xffffffffu, ss, o);
    if (lane == 0) sh[wid] = ss;
    __syncthreads();
    int nw = (blockDim.x + 31) >> 5;
    float tot = 0.f;
    if (threadIdx.x < nw) tot = sh[threadIdx.x];
    if (wid == 0) {
#pragma unroll
        for (int o = 16; o; o >>= 1) tot += __shfl_xor_sync(0xffffffffu, tot, o);
        if (lane == 0) sh[0] = tot;
    }
    __syncthreads();
    float inv = rsqrtf(sh[0] / (float)cols + eps);
    for (int j = threadIdx.x; j < cols; j += blockDim.x)
        op[j] = __float2half_rn(ip[j] * inv * w[j]);
}

// ------------------------- build Q/K/V with RoPE (fp16 out) --------------------
__global__ void build_qkv_k(const __half* __restrict__ qf, const __half* __restrict__ kvup,
                            const float* __restrict__ ckv,
                            const float* __restrict__ fcos, const float* __restrict__ fsin,
                            __half* __restrict__ Q, __half* __restrict__ K,
                            __half* __restrict__ V)
{
    const int i = blockIdx.x;
    const int tid = threadIdx.x;              // 128
    __shared__ float cs[8], sn[8];
    int p = i >> 2;
    if (tid < 8) {
        if (p == 0) { cs[tid] = 1.f; sn[tid] = 0.f; }
        else { cs[tid] = fcos[(p - 1) * 8 + tid]; sn[tid] = fsin[(p - 1) * 8 + tid]; }
    }
    __syncthreads();

    const __half* qrow = qf + (long long)i * 1536;
    const __half* krow = kvup + (long long)i * 2048;
    const float*  crow = ckv + (long long)i * 384;

    for (int e = tid; e < H2 * DQKP; e += 128) {
        int h2 = e / DQKP, d = e % DQKP;
        int h = h2 >> 1, c = h2 & 1;
        float qv = 0.f, kv = 0.f;
        if (d < 32) {
            qv = __half2float(qrow[h * 96 + c * 32 + d]);
            kv = __half2float(krow[h * 128 + c * 32 + d]);
        } else if (d < DQK) {
            int ee = d - 32;
            int f = ee >> 1;
            float q0 = __half2float(qrow[h * 96 + 64 + c * 16 + 2 * f]);
            float q1 = __half2float(qrow[h * 96 + 64 + c * 16 + 2 * f + 1]);
            float k0 = crow[KVCC + c * 16 + 2 * f];
            float k1 = crow[KVCC + c * 16 + 2 * f + 1];
            float C = cs[f], Sv = sn[f];
            if ((ee & 1) == 0) { qv = q0 * C - q1 * Sv; kv = k0 * C - k1 * Sv; }
            else               { qv = q0 * Sv + q1 * C; kv = k0 * Sv + k1 * C; }
        }
        Q[(long long)h2 * S_LEN * DQKP + (long long)i * DQKP + d] = __float2half_rn(qv);
        K[(long long)h2 * S_LEN * DQKP + (long long)i * DQKP + d] = __float2half_rn(kv);
    }
    for (int e = tid; e < NH * HD; e += 128) {
        int h = e >> 6, d = e & 63;
        V[(long long)h * S_LEN * HD + (long long)i * HD + d] = krow[h * 128 + 64 + d];
    }
}

// ---------- colmean stage 1: partial column sums over 128-row slabs ------------
__global__ void colmean_part_k(const __half* __restrict__ Ph, const float* __restrict__ invp,
                               float* __restrict__ gp)
{
    int j = blockIdx.x * blockDim.x + threadIdx.x;
    int h = blockIdx.y;
    int slab = blockIdx.z;
    if (j >= S_LEN) return;
    const __half* base = Ph + (long long)(2 * h) * S_LEN * S_LEN + j;
    const float*  iv   = invp + (2 * h) * S_LEN;
    int i0 = slab * 128;
    float s = 0.f;
#pragma unroll 4
    for (int i = i0; i < i0 + 128; i++)
        s += __half2float(base[(long long)i * S_LEN]) * iv[i];
    gp[((long long)slab * NH + h) * S_LEN + j] = s;
}
__global__ void colmean_red_k(const float* __restrict__ gp, float* __restrict__ g)
{
    int j = blockIdx.x * blockDim.x + threadIdx.x;
    int h = blockIdx.y;
    if (j >= S_LEN) return;
    float s = 0.f;
#pragma unroll
    for (int slab = 0; slab < 12; slab++)
        s += gp[((long long)slab * NH + h) * S_LEN + j];
    g[h * S_LEN + j] = s;
}

// ------------------------- lambda scalar -------------------------
__global__ void lambda_k_(const float* __restrict__ q1, const float* __restrict__ k1,
                          const float* __restrict__ q2, const float* __restrict__ k2,
                          float* __restrict__ out)
{
    int t = threadIdx.x;
    float a = q1[t] * k1[t];
    float b = q2[t] * k2[t];
#pragma unroll
    for (int o = 16; o; o >>= 1) {
        a += __shfl_xor_sync(0xffffffffu, a, o);
        b += __shfl_xor_sync(0xffffffffu, b, o);
    }
    if (t == 0) *out = expf(a) - expf(b) + LAMBDA_INIT;
}

// ------------------------- per (token, head) rmsnorm: fp32 -> fp16 -------------
__global__ void attn_norm_k(const float* __restrict__ ao, const float* __restrict__ w,
                            __half* __restrict__ outf)
{
    int i = blockIdx.x, h = blockIdx.y, d = threadIdx.x;
    long long idx = ((long long)h * S_LEN + i) * HD + d;
    float v = ao[idx];
    float sq = v * v;
    __shared__ float sh[2];
#pragma unroll
    for (int o = 16; o; o >>= 1) sq += __shfl_xor_sync(0xffffffffu, sq, o);
    if ((d & 31) == 0) sh[d >> 5] = sq;
    __syncthreads();
    float tot = sh[0] + sh[1];
    outf[idx] = __float2half_rn(v * rsqrtf(tot / (float)HD + ATTN_EPS) * w[d]);
}

// ------------------------- weight converts -------------------------
__global__ void cvt_h_k(const float* __restrict__ in, __half* __restrict__ out, int n)
{
    int i = (blockIdx.x * blockDim.x + threadIdx.x) * 4;
    int stride = gridDim.x * blockDim.x * 4;
    for (; i < n; i += stride) {
        float4 v = *(const float4*)(in + i);
        *(__half2*)(out + i)     = __floats2half2_rn(v.x, v.y);
        *(__half2*)(out + i + 2) = __floats2half2_rn(v.z, v.w);
    }
}
__global__ void cvt_swiglu_k(const float* __restrict__ in, __half* __restrict__ out)
{
    int i = (blockIdx.x * blockDim.x + threadIdx.x) * 4;
    int stride = gridDim.x * blockDim.x * 4;
    int n = 2 * DFF * DM;
    for (; i < n; i += stride) {
        int k = i / DM, d = i - k * DM;
        int orow = (k < DFF) ? (2 * k) : (2 * (k - DFF) + 1);
        float4 v = *(const float4*)(in + i);
        __half* dst = out + (long long)orow * DM + d;
        *(__half2*)(dst)     = __floats2half2_rn(v.x, v.y);
        *(__half2*)(dst + 2) = __floats2half2_rn(v.z, v.w);
    }
}
__global__ void zero_h_k(__half* __restrict__ p, int n)
{
    int i = blockIdx.x * blockDim.x + threadIdx.x;
    if (i < n) p[i] = __float2half(0.f);
}

// ------------------------- host -------------------------
extern "C" void kernel_launch(void* const* d_in, const int* in_sizes, int n_in,
                              void* d_out, int out_size)
{
    const float* x    = (const float*)d_in[0];
    const float* fc   = (const float*)d_in[1];
    const float* fs   = (const float*)d_in[2];
    const float* n1w  = (const float*)d_in[3];
    const float* n2w  = (const float*)d_in[4];
    const float* kvdw = (const float*)d_in[5];
    const float* qdw  = (const float*)d_in[6];
    const float* kvnw = (const float*)d_in[7];
    const float* qnw  = (const float*)d_in[8];
    const float* kvuw = (const float*)d_in[9];
    const float* quw  = (const float*)d_in[10];
    const float* lq1  = (const float*)d_in[11];
    const float* lk1  = (const float*)d_in[12];
    const float* lq2  = (const float*)d_in[13];
    const float* lk2  = (const float*)d_in[14];
    const float* anw  = (const float*)d_in[15];
    const float* ow   = (const float*)d_in[16];
    const float* fiw  = (const float*)d_in[17];
    const float* fow  = (const float*)d_in[18];
    float* outp = (float*)d_out;

    __half *xin, *ckvn, *kvup, *cqn, *qf, *Q, *K, *V, *Ph, *af, *hb, *act;
    __half *kvdw_h, *qdw_h, *kvuw_h, *quw_h, *ow_h, *fiw_h, *fow_h;
    float *ckv, *cq, *gg, *gp, *ao, *x2, *lam, *invp;
    cudaGetSymbolAddress((void**)&xin,  g_xin);
    cudaGetSymbolAddress((void**)&ckv,  g_ckv);
    cudaGetSymbolAddress((void**)&ckvn, g_ckvn);
    cudaGetSymbolAddress((void**)&kvup, g_kvup);
    cudaGetSymbolAddress((void**)&cq,   g_cq);
    cudaGetSymbolAddress((void**)&cqn,  g_cqn);
    cudaGetSymbolAddress((void**)&qf,   g_qf);
    cudaGetSymbolAddress((void**)&Q,    g_Q);
    cudaGetSymbolAddress((void**)&K,    g_K);
    cudaGetSymbolAddress((void**)&V,    g_V);
    cudaGetSymbolAddress((void**)&Ph,   g_Ph);
    cudaGetSymbolAddress((void**)&invp, g_inv);
    cudaGetSymbolAddress((void**)&gg,   g_g);
    cudaGetSymbolAddress((void**)&gp,   g_gp);
    cudaGetSymbolAddress((void**)&ao,   g_ao);
    cudaGetSymbolAddress((void**)&af,   g_af);
    cudaGetSymbolAddress((void**)&x2,   g_x2);
    cudaGetSymbolAddress((void**)&hb,   g_hb);
    cudaGetSymbolAddress((void**)&act,  g_act);
    cudaGetSymbolAddress((void**)&lam,  g_lambda);
    cudaGetSymbolAddress((void**)&kvdw_h, g_kvdw_h);
    cudaGetSymbolAddress((void**)&qdw_h,  g_qdw_h);
    cudaGetSymbolAddress((void**)&kvuw_h, g_kvuw_h);
    cudaGetSymbolAddress((void**)&quw_h,  g_quw_h);
    cudaGetSymbolAddress((void**)&ow_h,   g_ow_h);
    cudaGetSymbolAddress((void**)&fiw_h,  g_fiw_h);
    cudaGetSymbolAddress((void**)&fow_h,  g_fow_h);

    static bool attr_set = false;
    if (!attr_set) {
        cudaFuncSetAttribute((const void*)hgemm<0,128>, cudaFuncAttributeMaxDynamicSharedMemorySize, SMEM_H128);
        cudaFuncSetAttribute((const void*)hgemm<1,128>, cudaFuncAttributeMaxDynamicSharedMemorySize, SMEM_H128);
        cudaFuncSetAttribute((const void*)hgemm<2,128>, cudaFuncAttributeMaxDynamicSharedMemorySize, SMEM_H128);
        cudaFuncSetAttribute((const void*)hgemm<0,64>,  cudaFuncAttributeMaxDynamicSharedMemorySize, SMEM_H64);
        cudaFuncSetAttribute((const void*)hgemm<1,64>,  cudaFuncAttributeMaxDynamicSharedMemorySize, SMEM_H64);
        cudaFuncSetAttribute((const void*)qk_softmax_k, cudaFuncAttributeMaxDynamicSharedMemorySize, QK_SMEM);
        attr_set = true;
    }

    auto grid128 = [](int M, int N, int batch) {
        return dim3((unsigned)(N / 128), (unsigned)(M / 128), (unsigned)batch);
    };
    auto grid64 = [](int M, int N, int batch) {
        return dim3((unsigned)(N / 64), (unsigned)(M / 128), (unsigned)batch);
    };

    // 0. weights -> fp16 (+ zero-pad kv_down rows 288..383; ff_in interleaved)
    cvt_h_k<<<288,  256>>>(kvdw, kvdw_h, 288 * DM);
    zero_h_k<<<(96 * DM + 255) / 256, 256>>>(kvdw_h + 288 * DM, 96 * DM);
    cvt_h_k<<<384,  256>>>(qdw,  qdw_h,  QCC * DM);
    cvt_h_k<<<512,  256>>>(kvuw, kvuw_h, 2048 * KVCC);
    cvt_h_k<<<576,  256>>>(quw,  quw_h,  1536 * QCC);
    cvt_h_k<<<1024, 256>>>(ow,   ow_h,   DM * DM);
    cvt_swiglu_k<<<4096, 256>>>(fiw, fiw_h);
    cvt_h_k<<<4096, 256>>>(fow,  fow_h,  DM * DFF);

    // 1. xin = rmsnorm(x) -> fp16
    rmsnorm_h<<<S_LEN, 256>>>(x, n1w, xin, DM, DM, DM, EPS_RMS);
    // 2. ckv = xin @ kv_down^T [1536, 384(pad)] fp32  (N64: 72 CTAs)
    hgemm<0,64><<<grid64(S_LEN, 384, 1), 256, SMEM_H64>>>(xin, kvdw_h, nullptr, ckv,
        S_LEN, 384, DM, 0, 0, 0, 1.f);
    // 3. ckvn = rmsnorm(ckv[:, :256]) -> fp16
    rmsnorm_h<<<S_LEN, 256>>>(ckv, kvnw, ckvn, KVCC, 384, KVCC, EPS_RMS);
    // 4. kvup = ckvn @ kv_up^T [1536, 2048] fp16  (N64: 384 CTAs)
    hgemm<1,64><<<grid64(S_LEN, 2048, 1), 256, SMEM_H64>>>(ckvn, kvuw_h, nullptr, kvup,
        S_LEN, 2048, KVCC, 0, 0, 0, 1.f);
    // 5. cq = xin @ q_down^T [1536, 384] fp32  (N64: 72 CTAs)
    hgemm<0,64><<<grid64(S_LEN, QCC, 1), 256, SMEM_H64>>>(xin, qdw_h, nullptr, cq,
        S_LEN, QCC, DM, 0, 0, 0, 1.f);
    // 6. cqn = rmsnorm(cq) -> fp16
    rmsnorm_h<<<S_LEN, 256>>>(cq, qnw, cqn, QCC, QCC, QCC, EPS_RMS);
    // 7. qf = cqn @ q_up^T [1536, 1536] fp16  (N64: 288 CTAs)
    hgemm<1,64><<<grid64(S_LEN, 1536, 1), 256, SMEM_H64>>>(cqn, quw_h, nullptr, qf,
        S_LEN, 1536, QCC, 0, 0, 0, 1.f);
    // 8. build Q/K/V (fp16, Q/K padded to 64)
    build_qkv_k<<<S_LEN, 128>>>(qf, kvup, ckv, fc, fs, Q, K, V);
    // 9. fused QK^T + masked unnormalized softmax
    qk_softmax_k<<<dim3(S_LEN / 128, H2), 256, QK_SMEM>>>(Q, K, Ph, invp);
    // 10. lambda
    lambda_k_<<<1, 32>>>(lq1, lk1, lq2, lk2, lam);
    // 11. column sums (two-stage deterministic)
    colmean_part_k<<<dim3((S_LEN + 255) / 256, NH, 12), 256>>>(Ph, invp, gp);
    colmean_red_k<<<dim3((S_LEN + 255) / 256, NH), 256>>>(gp, gg);
    // 12+13. fused combine + AV (K-tile 64)
    av_k<<<dim3(S_LEN / AVM, NH), 256>>>(Ph, invp, V, gg, lam, ao);
    // 14. attn rmsnorm -> fp16
    attn_norm_k<<<dim3(S_LEN, NH), 64>>>(ao, anw, af);
    // 15. x2 = x + af @ o_w^T fp32  (N64: 192 CTAs)
    hgemm<0,64><<<grid64(S_LEN, DM, 1), 256, SMEM_H64>>>(af, ow_h, x, x2,
        S_LEN, DM, DM, 0, 0, 0, 1.f);
    // 16. hb = rmsnorm(x2) -> fp16
    rmsnorm_h<<<S_LEN, 256>>>(x2, n2w, hb, DM, DM, DM, EPS_RMS);
    // 17. act = swiglu(hb @ ff_in^T) [1536, 4096] fp16  (N128: 768 CTAs)
    hgemm<2,128><<<grid128(S_LEN, 2 * DFF, 1), 256, SMEM_H128>>>(hb, fiw_h, nullptr, act,
        S_LEN, 2 * DFF, DM, 0, 0, 0, 1.f);
    // 18. out = x2 + act @ ff_out^T fp32  (N64: 192 CTAs)
    hgemm<0,64><<<grid64(S_LEN, DM, 1), 256, SMEM_H64>>>(act, fow_h, x2, outp,
        S_LEN, DM, DFF, 0, 0, 0, 1.f);
}

// round 15
// speedup vs baseline: 1.0411x; 1.0411x over previous
#include <cuda_runtime.h>
#include <cuda_fp16.h>
#include <math.h>
#include <stdint.h>

#define S_LEN 1536
#define DM    1024
#define NH    16
#define HD    64
#define H2    32
#define DQK   48
#define DQKP  64
#define KVCC  256
#define ROPE_ 32
#define QCC   384
#define DFF   4096
#define SPP   384
#define EPS_RMS 1.1920929e-07f
#define ATTN_EPS 1e-5f
#define SCALING 0.14433756729740643f
#define LAMBDA_INIT 0.2f

// ------------------------- device scratch -------------------------
__device__ __half g_xin [S_LEN * DM];
__device__ float  g_ckv [S_LEN * 384];
__device__ __half g_ckvn[S_LEN * KVCC];
__device__ __half g_kvup[S_LEN * 2048];
__device__ float  g_cq  [S_LEN * QCC];
__device__ __half g_cqn [S_LEN * QCC];
__device__ __half g_qf  [S_LEN * 1536];
__device__ __half g_Q   [(size_t)H2 * S_LEN * DQKP];
__device__ __half g_K   [(size_t)H2 * S_LEN * DQKP];
__device__ __half g_V   [(size_t)NH * S_LEN * HD];
__device__ __half g_Ph  [(size_t)H2 * S_LEN * S_LEN];   // UNNORMALIZED exp, fp16
__device__ float  g_inv [H2 * S_LEN];                    // per-row 1/sum
__device__ float  g_g   [NH * S_LEN];
__device__ float  g_gp  [12 * NH * S_LEN];               // colmean partials
__device__ float  g_ao  [(size_t)NH * S_LEN * HD];
__device__ __half g_af  [S_LEN * DM];
__device__ float  g_x2  [S_LEN * DM];
__device__ __half g_hb  [S_LEN * DM];
__device__ __half g_act [(size_t)S_LEN * DFF];
__device__ float  g_lambda;
// fp16 weight copies
__device__ __half g_kvdw_h[384 * DM];
__device__ __half g_qdw_h [QCC * DM];
__device__ __half g_kvuw_h[2048 * KVCC];
__device__ __half g_quw_h [1536 * QCC];
__device__ __half g_ow_h  [(size_t)DM * DM];
__device__ __half g_fiw_h [(size_t)2 * DFF * DM];       // swiglu-interleaved rows
__device__ __half g_fow_h [(size_t)DM * DFF];

// ------------------------- helpers -------------------------
__device__ __forceinline__ void cpa16(void* smem_dst, const void* gsrc) {
    unsigned a = (unsigned)__cvta_generic_to_shared(smem_dst);
    asm volatile("cp.async.ca.shared.global [%0], [%1], 16;\n" :: "r"(a), "l"(gsrc));
}
__device__ __forceinline__ void cpa_commit() { asm volatile("cp.async.commit_group;\n"); }
template <int NG>
__device__ __forceinline__ void cpa_wait() { asm volatile("cp.async.wait_group %0;\n" :: "n"(NG)); }

#define LDM_X4(a0,a1,a2,a3,p) \
    asm volatile("ldmatrix.sync.aligned.m8n8.x4.shared.b16 {%0,%1,%2,%3}, [%4];" \
        : "=r"(a0), "=r"(a1), "=r"(a2), "=r"(a3) \
        : "r"((unsigned)__cvta_generic_to_shared(p)))
#define LDM_X2(b0,b1,p) \
    asm volatile("ldmatrix.sync.aligned.m8n8.x2.shared.b16 {%0,%1}, [%2];" \
        : "=r"(b0), "=r"(b1) \
        : "r"((unsigned)__cvta_generic_to_shared(p)))
#define LDM_X2T(b0,b1,p) \
    asm volatile("ldmatrix.sync.aligned.m8n8.x2.trans.shared.b16 {%0,%1}, [%2];" \
        : "=r"(b0), "=r"(b1) \
        : "r"((unsigned)__cvta_generic_to_shared(p)))
#define MMA_F16(d, a, b) \
    asm volatile( \
        "mma.sync.aligned.m16n8k16.row.col.f32.f16.f16.f32 " \
        "{%0,%1,%2,%3}, {%4,%5,%6,%7}, {%8,%9}, {%0,%1,%2,%3};" \
        : "+f"(d[0]), "+f"(d[1]), "+f"(d[2]), "+f"(d[3]) \
        : "r"(a[0]), "r"(a[1]), "r"(a[2]), "r"(a[3]), "r"(b[0]), "r"(b[1]))

#define KSTR 72     /* stride (halves) for 64-wide k-tiles */

// --------- FP16 GEMM: 128xNT tiles (NT=128 or 64), K-tile=64, 2-stage ----------
// MODE: 0 = fp32 out (+Res), 1 = fp16 out, 2 = swiglu fp16 out (paired cols)
#define SMEM_H128 (2 * (128 + 128) * KSTR * 2)
#define SMEM_H64  (2 * (128 + 64)  * KSTR * 2)

template <int MODE, int NT>
__global__ __launch_bounds__(256, 2)
void hgemm(const __half* __restrict__ A, const __half* __restrict__ B,
           const float* __restrict__ Res, void* __restrict__ Cv,
           int M, int N, int K, long long sA, long long sB, long long sC,
           float scale)
{
    constexpr int WN  = NT / 32;
    constexpr int WMT = (8 / WN) == 2 ? 4 : 2;
    constexpr int BCH = NT / 32;

    extern __shared__ __half hsm[];
    __half* AsB = hsm;
    __half* BsB = hsm + 2 * 128 * KSTR;

    A += (long long)blockIdx.z * sA;
    B += (long long)blockIdx.z * sB;
    float*  Cf = (float*)Cv  + (long long)blockIdx.z * sC;
    __half* Ch = (__half*)Cv + (long long)blockIdx.z * sC;

    const int tid  = threadIdx.x;
    const int lane = tid & 31;
    const int warp = tid >> 5;
    const int wm   = warp / WN;
    const int wn   = warp % WN;
    const int row0 = blockIdx.y * 128;
    const int col0 = blockIdx.x * NT;
    const int grp  = lane >> 2;
    const int tig  = lane & 3;

    const int nk = K / 64;

    auto load_tiles = [&](int ki, int buf) {
        const __half* Ag = A + (long long)row0 * K + ki * 64;
        __half* Ad = AsB + buf * 128 * KSTR;
#pragma unroll
        for (int it = 0; it < 4; it++) {
            int f = tid + it * 256;
            int r = f >> 3, c8 = (f & 7) * 8;
            cpa16(Ad + r * KSTR + c8, Ag + (long long)r * K + c8);
        }
        const __half* Bg = B + (long long)col0 * K + ki * 64;
        __half* Bd = BsB + buf * NT * KSTR;
#pragma unroll
        for (int it = 0; it < BCH; it++) {
            int f = tid + it * 256;
            int r = f >> 3, c8 = (f & 7) * 8;
            cpa16(Bd + r * KSTR + c8, Bg + (long long)r * K + c8);
        }
        cpa_commit();
    };

    float acc[WMT][4][4];
#pragma unroll
    for (int i = 0; i < WMT; i++)
#pragma unroll
        for (int j = 0; j < 4; j++)
#pragma unroll
            for (int l = 0; l < 4; l++) acc[i][j][l] = 0.f;

    load_tiles(0, 0);

    const int arow = (lane & 15);
    const int asel = (lane >> 4) * 8;
    const int brow = (lane & 7);
    const int bsel = ((lane >> 3) & 1) * 8;

    for (int i = 0; i < nk; i++) {
        int cur = i & 1;
        cpa_wait<0>();
        __syncthreads();
        if (i + 1 < nk) load_tiles(i + 1, cur ^ 1);

        const __half* Ab = AsB + cur * 128 * KSTR;
        const __half* Bb = BsB + cur * NT * KSTR;
#pragma unroll
        for (int kc = 0; kc < 4; kc++) {
            unsigned a[WMT][4], b[4][2];
            int acol = kc * 16 + asel;
            int bcol = kc * 16 + bsel;
#pragma unroll
            for (int mi = 0; mi < WMT; mi++) {
                const __half* p = Ab + (wm * (WMT * 16) + mi * 16 + arow) * KSTR + acol;
                LDM_X4(a[mi][0], a[mi][1], a[mi][2], a[mi][3], p);
            }
#pragma unroll
            for (int ni = 0; ni < 4; ni++) {
                const __half* p = Bb + (wn * 32 + ni * 8 + brow) * KSTR + bcol;
                LDM_X2(b[ni][0], b[ni][1], p);
            }
#pragma unroll
            for (int mi = 0; mi < WMT; mi++)
#pragma unroll
                for (int ni = 0; ni < 4; ni++)
                    MMA_F16(acc[mi][ni], a[mi], b[ni]);
        }
    }

#pragma unroll
    for (int mi = 0; mi < WMT; mi++)
#pragma unroll
        for (int ni = 0; ni < 4; ni++)
#pragma unroll
            for (int h = 0; h < 2; h++) {
                int r = row0 + wm * (WMT * 16) + mi * 16 + grp + h * 8;
                int cc = col0 + wn * 32 + ni * 8 + tig * 2;
                float v0 = acc[mi][ni][h * 2 + 0] * scale;
                float v1 = acc[mi][ni][h * 2 + 1] * scale;
                if (MODE == 2) {
                    float o = v0 * (v1 / (1.f + __expf(-v1)));
                    Ch[(long long)r * DFF + (cc >> 1)] = __float2half_rn(o);
                } else if (MODE == 1) {
                    *(__half2*)(Ch + (long long)r * N + cc) = __floats2half2_rn(v0, v1);
                } else {
                    long long o = (long long)r * N + cc;
                    if (Res) { v0 += Res[o]; v1 += Res[o + 1]; }
                    Cf[o] = v0; Cf[o + 1] = v1;
                }
            }
}

// --------- fused QK^T + masked unnormalized softmax (64-wide j-tiles) ----------
#define QKS 72
#define QK_SMEM (128*QKS*2 + 2*64*QKS*2 + 128*QKS*2)

__global__ __launch_bounds__(256)
void qk_softmax_k(const __half* __restrict__ Q, const __half* __restrict__ Kg,
                  __half* __restrict__ Ph, float* __restrict__ invp)
{
    extern __shared__ char qsm[];
    __half* Qs = (__half*)qsm;
    __half* Ks = Qs + 128 * QKS;
    __half* Os = Ks + 2 * 64 * QKS;

    const int h2   = blockIdx.y;
    const int row0 = blockIdx.x * 128;
    const int tid  = threadIdx.x;
    const int lane = tid & 31;
    const int warp = tid >> 5;
    const int grp  = lane >> 2;
    const int tig  = lane & 3;

    const __half* Qh = Q + (long long)h2 * S_LEN * DQKP;
    const __half* Kh = Kg + (long long)h2 * S_LEN * DQKP;
    __half* Pout = Ph + (long long)h2 * S_LEN * S_LEN;

#pragma unroll
    for (int it = 0; it < 4; it++) {
        int f = tid + it * 256, r = f >> 3, c8 = (f & 7) * 8;
        cpa16(Qs + r * QKS + c8, Qh + (long long)(row0 + r) * DQKP + c8);
    }
    cpa_commit();

    auto loadK = [&](int jt, int buf) {
#pragma unroll
        for (int it = 0; it < 2; it++) {
            int f = tid + it * 256, r = f >> 3, c8 = (f & 7) * 8;
            cpa16(Ks + buf * 64 * QKS + r * QKS + c8,
                  Kh + (long long)(jt * 64 + r) * DQKP + c8);
        }
        cpa_commit();
    };

    const int r0  = warp * 16 + grp;
    const int ip0 = (row0 + r0) % SPP;
    const int ip1 = (row0 + r0 + 8) % SPP;

    float s0 = 0.f, s1 = 0.f;

    loadK(0, 0);

    const int NJT = S_LEN / 64;
    for (int jt = 0; jt < NJT; jt++) {
        int buf = jt & 1;
        if (jt + 1 < NJT) { loadK(jt + 1, buf ^ 1); cpa_wait<1>(); }
        else              { cpa_wait<0>(); }
        __syncthreads();

        float acc[8][4];
#pragma unroll
        for (int ni = 0; ni < 8; ni++)
#pragma unroll
            for (int l = 0; l < 4; l++) acc[ni][l] = 0.f;

        const __half* Kb = Ks + buf * 64 * QKS;
#pragma unroll
        for (int kc = 0; kc < 4; kc++) {
            unsigned a[4];
            const __half* pa = Qs + (warp * 16 + (lane & 15)) * QKS
                                  + kc * 16 + (lane >> 4) * 8;
            LDM_X4(a[0], a[1], a[2], a[3], pa);
#pragma unroll
            for (int ni = 0; ni < 8; ni++) {
                unsigned bb[2];
                const __half* pb = Kb + (ni * 8 + (lane & 7)) * QKS
                                      + kc * 16 + ((lane >> 3) & 1) * 8;
                LDM_X2(bb[0], bb[1], pb);
                MMA_F16(acc[ni], a, bb);
            }
        }

#pragma unroll
        for (int ni = 0; ni < 8; ni++) {
            int c0  = jt * 64 + ni * 8 + tig * 2;
            int jm0 = c0 % SPP;
            float e00 = (jm0     <= ip0) ? __expf(fminf(acc[ni][0] * SCALING, 10.f)) : 0.f;
            float e01 = (jm0 + 1 <= ip0) ? __expf(fminf(acc[ni][1] * SCALING, 10.f)) : 0.f;
            float e10 = (jm0     <= ip1) ? __expf(fminf(acc[ni][2] * SCALING, 10.f)) : 0.f;
            float e11 = (jm0 + 1 <= ip1) ? __expf(fminf(acc[ni][3] * SCALING, 10.f)) : 0.f;
            s0 += e00 + e01;
            s1 += e10 + e11;
            *(__half2*)(Os + r0 * QKS + ni * 8 + tig * 2)       = __floats2half2_rn(e00, e01);
            *(__half2*)(Os + (r0 + 8) * QKS + ni * 8 + tig * 2) = __floats2half2_rn(e10, e11);
        }
        __syncthreads();

#pragma unroll
        for (int it = 0; it < 4; it++) {
            int f = tid + it * 256, r = f >> 3, c8 = (f & 7) * 8;
            uint4 u = *(uint4*)(Os + r * QKS + c8);
            *(uint4*)(Pout + (long long)(row0 + r) * S_LEN + jt * 64 + c8) = u;
        }
        __syncthreads();
    }

#pragma unroll
    for (int x = 1; x <= 2; x <<= 1) {
        s0 += __shfl_xor_sync(0xffffffffu, s0, x);
        s1 += __shfl_xor_sync(0xffffffffu, s1, x);
    }
    if (tig == 0) {
        invp[h2 * S_LEN + row0 + r0]     = 1.f / s0;
        invp[h2 * S_LEN + row0 + r0 + 8] = 1.f / s1;
    }
}

// --------------- fused differential-combine + AV GEMM, K-tile 64 ---------------
#define AVM 64

__global__ __launch_bounds__(256)
void av_k(const __half* __restrict__ Ph, const float* __restrict__ invp,
          const __half* __restrict__ V,
          const float* __restrict__ g, const float* __restrict__ lamp,
          float* __restrict__ O)
{
    __shared__ __half As[AVM * KSTR];
    __shared__ __half Bs[64 * KSTR];
    __shared__ float  sI1[AVM], sI2[AVM];

    const int h    = blockIdx.y;
    const int row0 = blockIdx.x * AVM;
    const int tid  = threadIdx.x;
    const int lane = tid & 31;
    const int warp = tid >> 5;
    const int wm   = warp >> 1;
    const int wn   = warp & 1;
    const int grp  = lane >> 2;
    const int tig  = lane & 3;

    const float lam = *lamp;
    const float gl  = lam * (1.f / (float)S_LEN);
    const __half* p1 = Ph + (long long)(2 * h) * S_LEN * S_LEN;
    const __half* p2 = Ph + (long long)(2 * h + 1) * S_LEN * S_LEN;
    const __half* Vh = V + (long long)h * S_LEN * HD;
    const float*  gh = g + h * S_LEN;

    if (tid < AVM) {
        sI1[tid] = invp[(2 * h) * S_LEN + row0 + tid];
        sI2[tid] = invp[(2 * h + 1) * S_LEN + row0 + tid];
    }
    __syncthreads();

    float acc[4][4];
#pragma unroll
    for (int j = 0; j < 4; j++)
#pragma unroll
        for (int l = 0; l < 4; l++) acc[j][l] = 0.f;

    for (int j0 = 0; j0 < S_LEN; j0 += 64) {
#pragma unroll
        for (int it = 0; it < 2; it++) {
            int f = tid + it * 256;
            int kk = f >> 3, c8 = (f & 7) * 8;
            cpa16(Bs + kk * KSTR + c8, Vh + (long long)(j0 + kk) * HD + c8);
        }
        cpa_commit();

#pragma unroll
        for (int it = 0; it < 2; it++) {
            int f = tid + it * 256;
            int r = f >> 3, c8 = (f & 7) * 8;
            int ip = (row0 + r) % SPP;
            float i1 = sI1[r], i2 = sI2[r];
            long long off = (long long)(row0 + r) * S_LEN + j0 + c8;
            uint4 u1 = *(const uint4*)(p1 + off);
            uint4 u2 = *(const uint4*)(p2 + off);
            const __half2* h1 = (const __half2*)&u1;
            const __half2* h2 = (const __half2*)&u2;
            __half outh[8];
            int jb = j0 + c8;
#pragma unroll
            for (int e = 0; e < 4; e++) {
                float2 f1 = __half22float2(h1[e]);
                float2 f2 = __half22float2(h2[e]);
                int ja = jb + 2 * e, jbb = ja + 1;
                float o0 = ((ja  % SPP) > ip) ? 0.f
                           : (f1.x * i1 - lam * (f2.x * i2) + gl * gh[ja]);
                float o1 = ((jbb % SPP) > ip) ? 0.f
                           : (f1.y * i1 - lam * (f2.y * i2) + gl * gh[jbb]);
                outh[2 * e]     = __float2half_rn(o0);
                outh[2 * e + 1] = __float2half_rn(o1);
            }
            *(uint4*)(As + r * KSTR + c8) = *(uint4*)outh;
        }
        cpa_wait<0>();
        __syncthreads();

#pragma unroll
        for (int kc = 0; kc < 4; kc++) {
            unsigned a[4], b[4][2];
            {
                const __half* p = As + (wm * 16 + (lane & 15)) * KSTR
                                     + kc * 16 + (lane >> 4) * 8;
                LDM_X4(a[0], a[1], a[2], a[3], p);
            }
#pragma unroll
            for (int ni = 0; ni < 4; ni++) {
                int krow = kc * 16 + ((lane >> 3) & 1) * 8 + (lane & 7);
                int ncol = wn * 32 + ni * 8;
                const __half* p = Bs + krow * KSTR + ncol;
                LDM_X2T(b[ni][0], b[ni][1], p);
            }
#pragma unroll
            for (int ni = 0; ni < 4; ni++)
                MMA_F16(acc[ni], a, b[ni]);
        }
        __syncthreads();
    }

#pragma unroll
    for (int ni = 0; ni < 4; ni++)
#pragma unroll
        for (int hh = 0; hh < 2; hh++) {
            int r = row0 + wm * 16 + grp + hh * 8;
            int cc = wn * 32 + ni * 8 + tig * 2;
            long long o = ((long long)h * S_LEN + r) * HD + cc;
            O[o]     = acc[ni][hh * 2 + 0];
            O[o + 1] = acc[ni][hh * 2 + 1];
        }
}

// ------------------------- rmsnorm: fp32 in -> fp16 out -------------------------
__global__ void rmsnorm_h(const float* __restrict__ in, const float* __restrict__ w,
                          __half* __restrict__ out, int cols, int in_ld, int out_ld,
                          float eps)
{
    const long long row = blockIdx.x;
    const float* ip = in + row * in_ld;
    __half* op = out + row * out_ld;

    float ss = 0.f;
    for (int j = threadIdx.x; j < cols; j += blockDim.x) {
        float v = ip[j];
        ss += v * v;
    }
    __shared__ float sh[32];
    int lane = threadIdx.x & 31, wid = threadIdx.x >> 5;
#pragma unroll
    for (int o = 16; o; o >>= 1) ss += __shfl_xor_sync(0xffffffffu, ss, o);
    if (lane == 0) sh[wid] = ss;
    __syncthreads();
    int nw = (blockDim.x + 31) >> 5;
    float tot = 0.f;
    if (threadIdx.x < nw) tot = sh[threadIdx.x];
    if (wid == 0) {
#pragma unroll
        for (int o = 16; o; o >>= 1) tot += __shfl_xor_sync(0xffffffffu, tot, o);
        if (lane == 0) sh[0] = tot;
    }
    __syncthreads();
    float inv = rsqrtf(sh[0] / (float)cols + eps);
    for (int j = threadIdx.x; j < cols; j += blockDim.x)
        op[j] = __float2half_rn(ip[j] * inv * w[j]);
}

// ------------------------- build Q/K/V with RoPE (fp16 out) --------------------
__global__ void build_qkv_k(const __half* __restrict__ qf, const __half* __restrict__ kvup,
                            const float* __restrict__ ckv,
                            const float* __restrict__ fcos, const float* __restrict__ fsin,
                            __half* __restrict__ Q, __half* __restrict__ K,
                            __half* __restrict__ V)
{
    const int i = blockIdx.x;
    const int tid = threadIdx.x;              // 128
    __shared__ float cs[8], sn[8];
    int p = i >> 2;
    if (tid < 8) {
        if (p == 0) { cs[tid] = 1.f; sn[tid] = 0.f; }
        else { cs[tid] = fcos[(p - 1) * 8 + tid]; sn[tid] = fsin[(p - 1) * 8 + tid]; }
    }
    __syncthreads();

    const __half* qrow = qf + (long long)i * 1536;
    const __half* krow = kvup + (long long)i * 2048;
    const float*  crow = ckv + (long long)i * 384;

    for (int e = tid; e < H2 * DQKP; e += 128) {
        int h2 = e / DQKP, d = e % DQKP;
        int h = h2 >> 1, c = h2 & 1;
        float qv = 0.f, kv = 0.f;
        if (d < 32) {
            qv = __half2float(qrow[h * 96 + c * 32 + d]);
            kv = __half2float(krow[h * 128 + c * 32 + d]);
        } else if (d < DQK) {
            int ee = d - 32;
            int f = ee >> 1;
            float q0 = __half2float(qrow[h * 96 + 64 + c * 16 + 2 * f]);
            float q1 = __half2float(qrow[h * 96 + 64 + c * 16 + 2 * f + 1]);
            float k0 = crow[KVCC + c * 16 + 2 * f];
            float k1 = crow[KVCC + c * 16 + 2 * f + 1];
            float C = cs[f], Sv = sn[f];
            if ((ee & 1) == 0) { qv = q0 * C - q1 * Sv; kv = k0 * C - k1 * Sv; }
            else               { qv = q0 * Sv + q1 * C; kv = k0 * Sv + k1 * C; }
        }
        Q[(long long)h2 * S_LEN * DQKP + (long long)i * DQKP + d] = __float2half_rn(qv);
        K[(long long)h2 * S_LEN * DQKP + (long long)i * DQKP + d] = __float2half_rn(kv);
    }
    for (int e = tid; e < NH * HD; e += 128) {
        int h = e >> 6, d = e & 63;
        V[(long long)h * S_LEN * HD + (long long)i * HD + d] = krow[h * 128 + 64 + d];
    }
}

// ---------- colmean stage 1: partial column sums over 128-row slabs ------------
__global__ void colmean_part_k(const __half* __restrict__ Ph, const float* __restrict__ invp,
                               float* __restrict__ gp)
{
    int j = blockIdx.x * blockDim.x + threadIdx.x;
    int h = blockIdx.y;
    int slab = blockIdx.z;
    if (j >= S_LEN) return;
    const __half* base = Ph + (long long)(2 * h) * S_LEN * S_LEN + j;
    const float*  iv   = invp + (2 * h) * S_LEN;
    int i0 = slab * 128;
    float s = 0.f;
#pragma unroll 4
    for (int i = i0; i < i0 + 128; i++)
        s += __half2float(base[(long long)i * S_LEN]) * iv[i];
    gp[((long long)slab * NH + h) * S_LEN + j] = s;
}
__global__ void colmean_red_k(const float* __restrict__ gp, float* __restrict__ g)
{
    int j = blockIdx.x * blockDim.x + threadIdx.x;
    int h = blockIdx.y;
    if (j >= S_LEN) return;
    float s = 0.f;
#pragma unroll
    for (int slab = 0; slab < 12; slab++)
        s += gp[((long long)slab * NH + h) * S_LEN + j];
    g[h * S_LEN + j] = s;
}

// ------------------------- lambda scalar -------------------------
__global__ void lambda_k_(const float* __restrict__ q1, const float* __restrict__ k1,
                          const float* __restrict__ q2, const float* __restrict__ k2,
                          float* __restrict__ out)
{
    int t = threadIdx.x;
    float a = q1[t] * k1[t];
    float b = q2[t] * k2[t];
#pragma unroll
    for (int o = 16; o; o >>= 1) {
        a += __shfl_xor_sync(0xffffffffu, a, o);
        b += __shfl_xor_sync(0xffffffffu, b, o);
    }
    if (t == 0) *out = expf(a) - expf(b) + LAMBDA_INIT;
}

// ------------------------- per (token, head) rmsnorm: fp32 -> fp16 -------------
__global__ void attn_norm_k(const float* __restrict__ ao, const float* __restrict__ w,
                            __half* __restrict__ outf)
{
    int i = blockIdx.x, h = blockIdx.y, d = threadIdx.x;
    long long idx = ((long long)h * S_LEN + i) * HD + d;
    float v = ao[idx];
    float sq = v * v;
    __shared__ float sh[2];
#pragma unroll
    for (int o = 16; o; o >>= 1) sq += __shfl_xor_sync(0xffffffffu, sq, o);
    if ((d & 31) == 0) sh[d >> 5] = sq;
    __syncthreads();
    float tot = sh[0] + sh[1];
    outf[idx] = __float2half_rn(v * rsqrtf(tot / (float)HD + ATTN_EPS) * w[d]);
}

// ------------------------- weight converts -------------------------
__global__ void cvt_h_k(const float* __restrict__ in, __half* __restrict__ out, int n)
{
    int i = (blockIdx.x * blockDim.x + threadIdx.x) * 4;
    int stride = gridDim.x * blockDim.x * 4;
    for (; i < n; i += stride) {
        float4 v = *(const float4*)(in + i);
        *(__half2*)(out + i)     = __floats2half2_rn(v.x, v.y);
        *(__half2*)(out + i + 2) = __floats2half2_rn(v.z, v.w);
    }
}
__global__ void cvt_swiglu_k(const float* __restrict__ in, __half* __restrict__ out)
{
    int i = (blockIdx.x * blockDim.x + threadIdx.x) * 4;
    int stride = gridDim.x * blockDim.x * 4;
    int n = 2 * DFF * DM;
    for (; i < n; i += stride) {
        int k = i / DM, d = i - k * DM;
        int orow = (k < DFF) ? (2 * k) : (2 * (k - DFF) + 1);
        float4 v = *(const float4*)(in + i);
        __half* dst = out + (long long)orow * DM + d;
        *(__half2*)(dst)     = __floats2half2_rn(v.x, v.y);
        *(__half2*)(dst + 2) = __floats2half2_rn(v.z, v.w);
    }
}
__global__ void zero_h_k(__half* __restrict__ p, int n)
{
    int i = blockIdx.x * blockDim.x + threadIdx.x;
    if (i < n) p[i] = __float2half(0.f);
}

// ------------------------- host -------------------------
extern "C" void kernel_launch(void* const* d_in, const int* in_sizes, int n_in,
                              void* d_out, int out_size)
{
    const float* x    = (const float*)d_in[0];
    const float* fc   = (const float*)d_in[1];
    const float* fs   = (const float*)d_in[2];
    const float* n1w  = (const float*)d_in[3];
    const float* n2w  = (const float*)d_in[4];
    const float* kvdw = (const float*)d_in[5];
    const float* qdw  = (const float*)d_in[6];
    const float* kvnw = (const float*)d_in[7];
    const float* qnw  = (const float*)d_in[8];
    const float* kvuw = (const float*)d_in[9];
    const float* quw  = (const float*)d_in[10];
    const float* lq1  = (const float*)d_in[11];
    const float* lk1  = (const float*)d_in[12];
    const float* lq2  = (const float*)d_in[13];
    const float* lk2  = (const float*)d_in[14];
    const float* anw  = (const float*)d_in[15];
    const float* ow   = (const float*)d_in[16];
    const float* fiw  = (const float*)d_in[17];
    const float* fow  = (const float*)d_in[18];
    float* outp = (float*)d_out;

    __half *xin, *ckvn, *kvup, *cqn, *qf, *Q, *K, *V, *Ph, *af, *hb, *act;
    __half *kvdw_h, *qdw_h, *kvuw_h, *quw_h, *ow_h, *fiw_h, *fow_h;
    float *ckv, *cq, *gg, *gp, *ao, *x2, *lam, *invp;
    cudaGetSymbolAddress((void**)&xin,  g_xin);
    cudaGetSymbolAddress((void**)&ckv,  g_ckv);
    cudaGetSymbolAddress((void**)&ckvn, g_ckvn);
    cudaGetSymbolAddress((void**)&kvup, g_kvup);
    cudaGetSymbolAddress((void**)&cq,   g_cq);
    cudaGetSymbolAddress((void**)&cqn,  g_cqn);
    cudaGetSymbolAddress((void**)&qf,   g_qf);
    cudaGetSymbolAddress((void**)&Q,    g_Q);
    cudaGetSymbolAddress((void**)&K,    g_K);
    cudaGetSymbolAddress((void**)&V,    g_V);
    cudaGetSymbolAddress((void**)&Ph,   g_Ph);
    cudaGetSymbolAddress((void**)&invp, g_inv);
    cudaGetSymbolAddress((void**)&gg,   g_g);
    cudaGetSymbolAddress((void**)&gp,   g_gp);
    cudaGetSymbolAddress((void**)&ao,   g_ao);
    cudaGetSymbolAddress((void**)&af,   g_af);
    cudaGetSymbolAddress((void**)&x2,   g_x2);
    cudaGetSymbolAddress((void**)&hb,   g_hb);
    cudaGetSymbolAddress((void**)&act,  g_act);
    cudaGetSymbolAddress((void**)&lam,  g_lambda);
    cudaGetSymbolAddress((void**)&kvdw_h, g_kvdw_h);
    cudaGetSymbolAddress((void**)&qdw_h,  g_qdw_h);
    cudaGetSymbolAddress((void**)&kvuw_h, g_kvuw_h);
    cudaGetSymbolAddress((void**)&quw_h,  g_quw_h);
    cudaGetSymbolAddress((void**)&ow_h,   g_ow_h);
    cudaGetSymbolAddress((void**)&fiw_h,  g_fiw_h);
    cudaGetSymbolAddress((void**)&fow_h,  g_fow_h);

    static bool attr_set = false;
    if (!attr_set) {
        cudaFuncSetAttribute((const void*)hgemm<0,128>, cudaFuncAttributeMaxDynamicSharedMemorySize, SMEM_H128);
        cudaFuncSetAttribute((const void*)hgemm<1,128>, cudaFuncAttributeMaxDynamicSharedMemorySize, SMEM_H128);
        cudaFuncSetAttribute((const void*)hgemm<2,128>, cudaFuncAttributeMaxDynamicSharedMemorySize, SMEM_H128);
        cudaFuncSetAttribute((const void*)hgemm<0,64>,  cudaFuncAttributeMaxDynamicSharedMemorySize, SMEM_H64);
        cudaFuncSetAttribute((const void*)qk_softmax_k, cudaFuncAttributeMaxDynamicSharedMemorySize, QK_SMEM);
        attr_set = true;
    }

    auto grid128 = [](int M, int N, int batch) {
        return dim3((unsigned)(N / 128), (unsigned)(M / 128), (unsigned)batch);
    };
    auto grid64 = [](int M, int N, int batch) {
        return dim3((unsigned)(N / 64), (unsigned)(M / 128), (unsigned)batch);
    };

    // 0. weights -> fp16 (+ zero-pad kv_down rows 288..383; ff_in interleaved)
    cvt_h_k<<<288,  256>>>(kvdw, kvdw_h, 288 * DM);
    zero_h_k<<<(96 * DM + 255) / 256, 256>>>(kvdw_h + 288 * DM, 96 * DM);
    cvt_h_k<<<384,  256>>>(qdw,  qdw_h,  QCC * DM);
    cvt_h_k<<<512,  256>>>(kvuw, kvuw_h, 2048 * KVCC);
    cvt_h_k<<<576,  256>>>(quw,  quw_h,  1536 * QCC);
    cvt_h_k<<<1024, 256>>>(ow,   ow_h,   DM * DM);
    cvt_swiglu_k<<<4096, 256>>>(fiw, fiw_h);
    cvt_h_k<<<4096, 256>>>(fow,  fow_h,  DM * DFF);

    // 1. xin = rmsnorm(x) -> fp16
    rmsnorm_h<<<S_LEN, 256>>>(x, n1w, xin, DM, DM, DM, EPS_RMS);
    // 2. ckv = xin @ kv_down^T [1536, 384(pad)] fp32  (N64: 72 CTAs — starved GEMM)
    hgemm<0,64><<<grid64(S_LEN, 384, 1), 256, SMEM_H64>>>(xin, kvdw_h, nullptr, ckv,
        S_LEN, 384, DM, 0, 0, 0, 1.f);
    // 3. ckvn = rmsnorm(ckv[:, :256]) -> fp16
    rmsnorm_h<<<S_LEN, 256>>>(ckv, kvnw, ckvn, KVCC, 384, KVCC, EPS_RMS);
    // 4. kvup = ckvn @ kv_up^T [1536, 2048] fp16  (N128: 192 CTAs)
    hgemm<1,128><<<grid128(S_LEN, 2048, 1), 256, SMEM_H128>>>(ckvn, kvuw_h, nullptr, kvup,
        S_LEN, 2048, KVCC, 0, 0, 0, 1.f);
    // 5. cq = xin @ q_down^T [1536, 384] fp32  (N64: 72 CTAs — starved GEMM)
    hgemm<0,64><<<grid64(S_LEN, QCC, 1), 256, SMEM_H64>>>(xin, qdw_h, nullptr, cq,
        S_LEN, QCC, DM, 0, 0, 0, 1.f);
    // 6. cqn = rmsnorm(cq) -> fp16
    rmsnorm_h<<<S_LEN, 256>>>(cq, qnw, cqn, QCC, QCC, QCC, EPS_RMS);
    // 7. qf = cqn @ q_up^T [1536, 1536] fp16  (N128: 144 CTAs)
    hgemm<1,128><<<grid128(S_LEN, 1536, 1), 256, SMEM_H128>>>(cqn, quw_h, nullptr, qf,
        S_LEN, 1536, QCC, 0, 0, 0, 1.f);
    // 8. build Q/K/V (fp16, Q/K padded to 64)
    build_qkv_k<<<S_LEN, 128>>>(qf, kvup, ckv, fc, fs, Q, K, V);
    // 9. fused QK^T + masked unnormalized softmax
    qk_softmax_k<<<dim3(S_LEN / 128, H2), 256, QK_SMEM>>>(Q, K, Ph, invp);
    // 10. lambda
    lambda_k_<<<1, 32>>>(lq1, lk1, lq2, lk2, lam);
    // 11. column sums (two-stage deterministic)
    colmean_part_k<<<dim3((S_LEN + 255) / 256, NH, 12), 256>>>(Ph, invp, gp);
    colmean_red_k<<<dim3((S_LEN + 255) / 256, NH), 256>>>(gp, gg);
    // 12+13. fused combine + AV (K-tile 64)
    av_k<<<dim3(S_LEN / AVM, NH), 256>>>(Ph, invp, V, gg, lam, ao);
    // 14. attn rmsnorm -> fp16
    attn_norm_k<<<dim3(S_LEN, NH), 64>>>(ao, anw, af);
    // 15. x2 = x + af @ o_w^T fp32  (N128: 96 CTAs)
    hgemm<0,128><<<grid128(S_LEN, DM, 1), 256, SMEM_H128>>>(af, ow_h, x, x2,
        S_LEN, DM, DM, 0, 0, 0, 1.f);
    // 16. hb = rmsnorm(x2) -> fp16
    rmsnorm_h<<<S_LEN, 256>>>(x2, n2w, hb, DM, DM, DM, EPS_RMS);
    // 17. act = swiglu(hb @ ff_in^T) [1536, 4096] fp16  (N128: 768 CTAs)
    hgemm<2,128><<<grid128(S_LEN, 2 * DFF, 1), 256, SMEM_H128>>>(hb, fiw_h, nullptr, act,
        S_LEN, 2 * DFF, DM, 0, 0, 0, 1.f);
    // 18. out = x2 + act @ ff_out^T fp32  (N128: 96 CTAs)
    hgemm<0,128><<<grid128(S_LEN, DM, 1), 256, SMEM_H128>>>(act, fow_h, x2, outp,
        S_LEN, DM, DFF, 0, 0, 0, 1.f);
}

// round 16
// speedup vs baseline: 1.0607x; 1.0188x over previous
#include <cuda_runtime.h>
#include <cuda_fp16.h>
#include <math.h>
#include <stdint.h>

#define S_LEN 1536
#define DM    1024
#define NH    16
#define HD    64
#define H2    32
#define DQK   48
#define DQKP  64
#define KVCC  256
#define ROPE_ 32
#define QCC   384
#define DFF   4096
#define SPP   384
#define EPS_RMS 1.1920929e-07f
#define ATTN_EPS 1e-5f
#define SCALING 0.14433756729740643f
#define LAMBDA_INIT 0.2f

// ------------------------- device scratch -------------------------
__device__ __half g_xin [S_LEN * DM];
__device__ float  g_ckv [S_LEN * 384];
__device__ __half g_ckvn[S_LEN * KVCC];
__device__ __half g_kvup[S_LEN * 2048];
__device__ float  g_cq  [S_LEN * QCC];
__device__ __half g_cqn [S_LEN * QCC];
__device__ __half g_qf  [S_LEN * 1536];
__device__ __half g_Q   [(size_t)H2 * S_LEN * DQKP];
__device__ __half g_K   [(size_t)H2 * S_LEN * DQKP];
__device__ __half g_V   [(size_t)NH * S_LEN * HD];
__device__ __half g_Ph  [(size_t)H2 * S_LEN * S_LEN];   // UNNORMALIZED exp, fp16
__device__ float  g_inv [H2 * S_LEN];                    // per-row 1/sum
__device__ float  g_g   [NH * S_LEN];
__device__ float  g_gp  [12 * NH * S_LEN];               // colmean partials
__device__ float  g_ao  [(size_t)NH * S_LEN * HD];
__device__ __half g_af  [S_LEN * DM];
__device__ float  g_x2  [S_LEN * DM];
__device__ __half g_hb  [S_LEN * DM];
__device__ __half g_act [(size_t)S_LEN * DFF];
__device__ float  g_lambda;
// fp16 weight copies
__device__ __half g_kvdw_h[384 * DM];
__device__ __half g_qdw_h [QCC * DM];
__device__ __half g_kvuw_h[2048 * KVCC];
__device__ __half g_quw_h [1536 * QCC];
__device__ __half g_ow_h  [(size_t)DM * DM];
__device__ __half g_fiw_h [(size_t)2 * DFF * DM];       // swiglu-interleaved rows
__device__ __half g_fow_h [(size_t)DM * DFF];

// ------------------------- helpers -------------------------
__device__ __forceinline__ void cpa16(void* smem_dst, const void* gsrc) {
    unsigned a = (unsigned)__cvta_generic_to_shared(smem_dst);
    asm volatile("cp.async.ca.shared.global [%0], [%1], 16;\n" :: "r"(a), "l"(gsrc));
}
__device__ __forceinline__ void cpa_commit() { asm volatile("cp.async.commit_group;\n"); }
template <int NG>
__device__ __forceinline__ void cpa_wait() { asm volatile("cp.async.wait_group %0;\n" :: "n"(NG)); }

#define LDM_X4(a0,a1,a2,a3,p) \
    asm volatile("ldmatrix.sync.aligned.m8n8.x4.shared.b16 {%0,%1,%2,%3}, [%4];" \
        : "=r"(a0), "=r"(a1), "=r"(a2), "=r"(a3) \
        : "r"((unsigned)__cvta_generic_to_shared(p)))
#define LDM_X2(b0,b1,p) \
    asm volatile("ldmatrix.sync.aligned.m8n8.x2.shared.b16 {%0,%1}, [%2];" \
        : "=r"(b0), "=r"(b1) \
        : "r"((unsigned)__cvta_generic_to_shared(p)))
#define LDM_X2T(b0,b1,p) \
    asm volatile("ldmatrix.sync.aligned.m8n8.x2.trans.shared.b16 {%0,%1}, [%2];" \
        : "=r"(b0), "=r"(b1) \
        : "r"((unsigned)__cvta_generic_to_shared(p)))
#define MMA_F16(d, a, b) \
    asm volatile( \
        "mma.sync.aligned.m16n8k16.row.col.f32.f16.f16.f32 " \
        "{%0,%1,%2,%3}, {%4,%5,%6,%7}, {%8,%9}, {%0,%1,%2,%3};" \
        : "+f"(d[0]), "+f"(d[1]), "+f"(d[2]), "+f"(d[3]) \
        : "r"(a[0]), "r"(a[1]), "r"(a[2]), "r"(a[3]), "r"(b[0]), "r"(b[1]))

#define KSTR 72     /* stride (halves) for 64-wide k-tiles */

// --------- FP16 GEMM: 128xNT tiles (NT=128 or 64), K-tile=64, 2-stage ----------
// MODE: 0 = fp32 out (+Res), 1 = fp16 out, 2 = swiglu fp16 out (paired cols)
#define SMEM_H128 (2 * (128 + 128) * KSTR * 2)
#define SMEM_H64  (2 * (128 + 64)  * KSTR * 2)

template <int MODE, int NT>
__global__ __launch_bounds__(256, 2)
void hgemm(const __half* __restrict__ A, const __half* __restrict__ B,
           const float* __restrict__ Res, void* __restrict__ Cv,
           int M, int N, int K, long long sA, long long sB, long long sC,
           float scale)
{
    constexpr int WN  = NT / 32;
    constexpr int WMT = (8 / WN) == 2 ? 4 : 2;
    constexpr int BCH = NT / 32;

    extern __shared__ __half hsm[];
    __half* AsB = hsm;
    __half* BsB = hsm + 2 * 128 * KSTR;

    A += (long long)blockIdx.z * sA;
    B += (long long)blockIdx.z * sB;
    float*  Cf = (float*)Cv  + (long long)blockIdx.z * sC;
    __half* Ch = (__half*)Cv + (long long)blockIdx.z * sC;

    const int tid  = threadIdx.x;
    const int lane = tid & 31;
    const int warp = tid >> 5;
    const int wm   = warp / WN;
    const int wn   = warp % WN;
    const int row0 = blockIdx.y * 128;
    const int col0 = blockIdx.x * NT;
    const int grp  = lane >> 2;
    const int tig  = lane & 3;

    const int nk = K / 64;

    auto load_tiles = [&](int ki, int buf) {
        const __half* Ag = A + (long long)row0 * K + ki * 64;
        __half* Ad = AsB + buf * 128 * KSTR;
#pragma unroll
        for (int it = 0; it < 4; it++) {
            int f = tid + it * 256;
            int r = f >> 3, c8 = (f & 7) * 8;
            cpa16(Ad + r * KSTR + c8, Ag + (long long)r * K + c8);
        }
        const __half* Bg = B + (long long)col0 * K + ki * 64;
        __half* Bd = BsB + buf * NT * KSTR;
#pragma unroll
        for (int it = 0; it < BCH; it++) {
            int f = tid + it * 256;
            int r = f >> 3, c8 = (f & 7) * 8;
            cpa16(Bd + r * KSTR + c8, Bg + (long long)r * K + c8);
        }
        cpa_commit();
    };

    float acc[WMT][4][4];
#pragma unroll
    for (int i = 0; i < WMT; i++)
#pragma unroll
        for (int j = 0; j < 4; j++)
#pragma unroll
            for (int l = 0; l < 4; l++) acc[i][j][l] = 0.f;

    load_tiles(0, 0);

    const int arow = (lane & 15);
    const int asel = (lane >> 4) * 8;
    const int brow = (lane & 7);
    const int bsel = ((lane >> 3) & 1) * 8;

    for (int i = 0; i < nk; i++) {
        int cur = i & 1;
        cpa_wait<0>();
        __syncthreads();
        if (i + 1 < nk) load_tiles(i + 1, cur ^ 1);

        const __half* Ab = AsB + cur * 128 * KSTR;
        const __half* Bb = BsB + cur * NT * KSTR;
#pragma unroll
        for (int kc = 0; kc < 4; kc++) {
            unsigned a[WMT][4], b[4][2];
            int acol = kc * 16 + asel;
            int bcol = kc * 16 + bsel;
#pragma unroll
            for (int mi = 0; mi < WMT; mi++) {
                const __half* p = Ab + (wm * (WMT * 16) + mi * 16 + arow) * KSTR + acol;
                LDM_X4(a[mi][0], a[mi][1], a[mi][2], a[mi][3], p);
            }
#pragma unroll
            for (int ni = 0; ni < 4; ni++) {
                const __half* p = Bb + (wn * 32 + ni * 8 + brow) * KSTR + bcol;
                LDM_X2(b[ni][0], b[ni][1], p);
            }
#pragma unroll
            for (int mi = 0; mi < WMT; mi++)
#pragma unroll
                for (int ni = 0; ni < 4; ni++)
                    MMA_F16(acc[mi][ni], a[mi], b[ni]);
        }
    }

#pragma unroll
    for (int mi = 0; mi < WMT; mi++)
#pragma unroll
        for (int ni = 0; ni < 4; ni++)
#pragma unroll
            for (int h = 0; h < 2; h++) {
                int r = row0 + wm * (WMT * 16) + mi * 16 + grp + h * 8;
                int cc = col0 + wn * 32 + ni * 8 + tig * 2;
                float v0 = acc[mi][ni][h * 2 + 0] * scale;
                float v1 = acc[mi][ni][h * 2 + 1] * scale;
                if (MODE == 2) {
                    float o = v0 * (v1 / (1.f + __expf(-v1)));
                    Ch[(long long)r * DFF + (cc >> 1)] = __float2half_rn(o);
                } else if (MODE == 1) {
                    *(__half2*)(Ch + (long long)r * N + cc) = __floats2half2_rn(v0, v1);
                } else {
                    long long o = (long long)r * N + cc;
                    if (Res) { v0 += Res[o]; v1 += Res[o + 1]; }
                    Cf[o] = v0; Cf[o + 1] = v1;
                }
            }
}

// --------- fused QK^T + masked unnormalized softmax (64-wide j-tiles) ----------
#define QKS 72
#define QK_SMEM (128*QKS*2 + 2*64*QKS*2 + 128*QKS*2)

__global__ __launch_bounds__(256)
void qk_softmax_k(const __half* __restrict__ Q, const __half* __restrict__ Kg,
                  __half* __restrict__ Ph, float* __restrict__ invp)
{
    extern __shared__ char qsm[];
    __half* Qs = (__half*)qsm;
    __half* Ks = Qs + 128 * QKS;
    __half* Os = Ks + 2 * 64 * QKS;

    const int h2   = blockIdx.y;
    const int row0 = blockIdx.x * 128;
    const int tid  = threadIdx.x;
    const int lane = tid & 31;
    const int warp = tid >> 5;
    const int grp  = lane >> 2;
    const int tig  = lane & 3;

    const __half* Qh = Q + (long long)h2 * S_LEN * DQKP;
    const __half* Kh = Kg + (long long)h2 * S_LEN * DQKP;
    __half* Pout = Ph + (long long)h2 * S_LEN * S_LEN;

#pragma unroll
    for (int it = 0; it < 4; it++) {
        int f = tid + it * 256, r = f >> 3, c8 = (f & 7) * 8;
        cpa16(Qs + r * QKS + c8, Qh + (long long)(row0 + r) * DQKP + c8);
    }
    cpa_commit();

    auto loadK = [&](int jt, int buf) {
#pragma unroll
        for (int it = 0; it < 2; it++) {
            int f = tid + it * 256, r = f >> 3, c8 = (f & 7) * 8;
            cpa16(Ks + buf * 64 * QKS + r * QKS + c8,
                  Kh + (long long)(jt * 64 + r) * DQKP + c8);
        }
        cpa_commit();
    };

    const int r0  = warp * 16 + grp;
    const int ip0 = (row0 + r0) % SPP;
    const int ip1 = (row0 + r0 + 8) % SPP;

    float s0 = 0.f, s1 = 0.f;

    loadK(0, 0);

    const int NJT = S_LEN / 64;
    for (int jt = 0; jt < NJT; jt++) {
        int buf = jt & 1;
        if (jt + 1 < NJT) { loadK(jt + 1, buf ^ 1); cpa_wait<1>(); }
        else              { cpa_wait<0>(); }
        __syncthreads();

        float acc[8][4];
#pragma unroll
        for (int ni = 0; ni < 8; ni++)
#pragma unroll
            for (int l = 0; l < 4; l++) acc[ni][l] = 0.f;

        const __half* Kb = Ks + buf * 64 * QKS;
#pragma unroll
        for (int kc = 0; kc < 4; kc++) {
            unsigned a[4];
            const __half* pa = Qs + (warp * 16 + (lane & 15)) * QKS
                                  + kc * 16 + (lane >> 4) * 8;
            LDM_X4(a[0], a[1], a[2], a[3], pa);
#pragma unroll
            for (int ni = 0; ni < 8; ni++) {
                unsigned bb[2];
                const __half* pb = Kb + (ni * 8 + (lane & 7)) * QKS
                                      + kc * 16 + ((lane >> 3) & 1) * 8;
                LDM_X2(bb[0], bb[1], pb);
                MMA_F16(acc[ni], a, bb);
            }
        }

#pragma unroll
        for (int ni = 0; ni < 8; ni++) {
            int c0  = jt * 64 + ni * 8 + tig * 2;
            int jm0 = c0 % SPP;
            float e00 = (jm0     <= ip0) ? __expf(fminf(acc[ni][0] * SCALING, 10.f)) : 0.f;
            float e01 = (jm0 + 1 <= ip0) ? __expf(fminf(acc[ni][1] * SCALING, 10.f)) : 0.f;
            float e10 = (jm0     <= ip1) ? __expf(fminf(acc[ni][2] * SCALING, 10.f)) : 0.f;
            float e11 = (jm0 + 1 <= ip1) ? __expf(fminf(acc[ni][3] * SCALING, 10.f)) : 0.f;
            s0 += e00 + e01;
            s1 += e10 + e11;
            *(__half2*)(Os + r0 * QKS + ni * 8 + tig * 2)       = __floats2half2_rn(e00, e01);
            *(__half2*)(Os + (r0 + 8) * QKS + ni * 8 + tig * 2) = __floats2half2_rn(e10, e11);
        }
        __syncthreads();

#pragma unroll
        for (int it = 0; it < 4; it++) {
            int f = tid + it * 256, r = f >> 3, c8 = (f & 7) * 8;
            uint4 u = *(uint4*)(Os + r * QKS + c8);
            *(uint4*)(Pout + (long long)(row0 + r) * S_LEN + jt * 64 + c8) = u;
        }
        __syncthreads();
    }

#pragma unroll
    for (int x = 1; x <= 2; x <<= 1) {
        s0 += __shfl_xor_sync(0xffffffffu, s0, x);
        s1 += __shfl_xor_sync(0xffffffffu, s1, x);
    }
    if (tig == 0) {
        invp[h2 * S_LEN + row0 + r0]     = 1.f / s0;
        invp[h2 * S_LEN + row0 + r0 + 8] = 1.f / s1;
    }
}

// --------------- fused differential-combine + AV GEMM, K-tile 64 ---------------
#define AVM 64

__global__ __launch_bounds__(256)
void av_k(const __half* __restrict__ Ph, const float* __restrict__ invp,
          const __half* __restrict__ V,
          const float* __restrict__ g, const float* __restrict__ lamp,
          float* __restrict__ O)
{
    __shared__ __half As[AVM * KSTR];
    __shared__ __half Bs[64 * KSTR];
    __shared__ float  sI1[AVM], sI2[AVM];

    const int h    = blockIdx.y;
    const int row0 = blockIdx.x * AVM;
    const int tid  = threadIdx.x;
    const int lane = tid & 31;
    const int warp = tid >> 5;
    const int wm   = warp >> 1;
    const int wn   = warp & 1;
    const int grp  = lane >> 2;
    const int tig  = lane & 3;

    const float lam = *lamp;
    const float gl  = lam * (1.f / (float)S_LEN);
    const __half* p1 = Ph + (long long)(2 * h) * S_LEN * S_LEN;
    const __half* p2 = Ph + (long long)(2 * h + 1) * S_LEN * S_LEN;
    const __half* Vh = V + (long long)h * S_LEN * HD;
    const float*  gh = g + h * S_LEN;

    if (tid < AVM) {
        sI1[tid] = invp[(2 * h) * S_LEN + row0 + tid];
        sI2[tid] = invp[(2 * h + 1) * S_LEN + row0 + tid];
    }
    __syncthreads();

    float acc[4][4];
#pragma unroll
    for (int j = 0; j < 4; j++)
#pragma unroll
        for (int l = 0; l < 4; l++) acc[j][l] = 0.f;

    for (int j0 = 0; j0 < S_LEN; j0 += 64) {
#pragma unroll
        for (int it = 0; it < 2; it++) {
            int f = tid + it * 256;
            int kk = f >> 3, c8 = (f & 7) * 8;
            cpa16(Bs + kk * KSTR + c8, Vh + (long long)(j0 + kk) * HD + c8);
        }
        cpa_commit();

#pragma unroll
        for (int it = 0; it < 2; it++) {
            int f = tid + it * 256;
            int r = f >> 3, c8 = (f & 7) * 8;
            int ip = (row0 + r) % SPP;
            float i1 = sI1[r], i2 = sI2[r];
            long long off = (long long)(row0 + r) * S_LEN + j0 + c8;
            uint4 u1 = *(const uint4*)(p1 + off);
            uint4 u2 = *(const uint4*)(p2 + off);
            const __half2* h1 = (const __half2*)&u1;
            const __half2* h2 = (const __half2*)&u2;
            __half outh[8];
            int jb = j0 + c8;
#pragma unroll
            for (int e = 0; e < 4; e++) {
                float2 f1 = __half22float2(h1[e]);
                float2 f2 = __half22float2(h2[e]);
                int ja = jb + 2 * e, jbb = ja + 1;
                float o0 = ((ja  % SPP) > ip) ? 0.f
                           : (f1.x * i1 - lam * (f2.x * i2) + gl * gh[ja]);
                float o1 = ((jbb % SPP) > ip) ? 0.f
                           : (f1.y * i1 - lam * (f2.y * i2) + gl * gh[jbb]);
                outh[2 * e]     = __float2half_rn(o0);
                outh[2 * e + 1] = __float2half_rn(o1);
            }
            *(uint4*)(As + r * KSTR + c8) = *(uint4*)outh;
        }
        cpa_wait<0>();
        __syncthreads();

#pragma unroll
        for (int kc = 0; kc < 4; kc++) {
            unsigned a[4], b[4][2];
            {
                const __half* p = As + (wm * 16 + (lane & 15)) * KSTR
                                     + kc * 16 + (lane >> 4) * 8;
                LDM_X4(a[0], a[1], a[2], a[3], p);
            }
#pragma unroll
            for (int ni = 0; ni < 4; ni++) {
                int krow = kc * 16 + ((lane >> 3) & 1) * 8 + (lane & 7);
                int ncol = wn * 32 + ni * 8;
                const __half* p = Bs + krow * KSTR + ncol;
                LDM_X2T(b[ni][0], b[ni][1], p);
            }
#pragma unroll
            for (int ni = 0; ni < 4; ni++)
                MMA_F16(acc[ni], a, b[ni]);
        }
        __syncthreads();
    }

#pragma unroll
    for (int ni = 0; ni < 4; ni++)
#pragma unroll
        for (int hh = 0; hh < 2; hh++) {
            int r = row0 + wm * 16 + grp + hh * 8;
            int cc = wn * 32 + ni * 8 + tig * 2;
            long long o = ((long long)h * S_LEN + r) * HD + cc;
            O[o]     = acc[ni][hh * 2 + 0];
            O[o + 1] = acc[ni][hh * 2 + 1];
        }
}

// ------------------------- rmsnorm: fp32 in -> fp16 out -------------------------
__global__ void rmsnorm_h(const float* __restrict__ in, const float* __restrict__ w,
                          __half* __restrict__ out, int cols, int in_ld, int out_ld,
                          float eps)
{
    const long long row = blockIdx.x;
    const float* ip = in + row * in_ld;
    __half* op = out + row * out_ld;

    float ss = 0.f;
    for (int j = threadIdx.x; j < cols; j += blockDim.x) {
        float v = ip[j];
        ss += v * v;
    }
    __shared__ float sh[32];
    int lane = threadIdx.x & 31, wid = threadIdx.x >> 5;
#pragma unroll
    for (int o = 16; o; o >>= 1) ss += __shfl_xor_sync(0xffffffffu, ss, o);
    if (lane == 0) sh[wid] = ss;
    __syncthreads();
    int nw = (blockDim.x + 31) >> 5;
    float tot = 0.f;
    if (threadIdx.x < nw) tot = sh[threadIdx.x];
    if (wid == 0) {
#pragma unroll
        for (int o = 16; o; o >>= 1) tot += __shfl_xor_sync(0xffffffffu, tot, o);
        if (lane == 0) sh[0] = tot;
    }
    __syncthreads();
    float inv = rsqrtf(sh[0] / (float)cols + eps);
    for (int j = threadIdx.x; j < cols; j += blockDim.x)
        op[j] = __float2half_rn(ip[j] * inv * w[j]);
}

// ------------------------- build Q/K/V with RoPE (fp16 out) --------------------
__global__ void build_qkv_k(const __half* __restrict__ qf, const __half* __restrict__ kvup,
                            const float* __restrict__ ckv,
                            const float* __restrict__ fcos, const float* __restrict__ fsin,
                            __half* __restrict__ Q, __half* __restrict__ K,
                            __half* __restrict__ V)
{
    const int i = blockIdx.x;
    const int tid = threadIdx.x;              // 128
    __shared__ float cs[8], sn[8];
    int p = i >> 2;
    if (tid < 8) {
        if (p == 0) { cs[tid] = 1.f; sn[tid] = 0.f; }
        else { cs[tid] = fcos[(p - 1) * 8 + tid]; sn[tid] = fsin[(p - 1) * 8 + tid]; }
    }
    __syncthreads();

    const __half* qrow = qf + (long long)i * 1536;
    const __half* krow = kvup + (long long)i * 2048;
    const float*  crow = ckv + (long long)i * 384;

    for (int e = tid; e < H2 * DQKP; e += 128) {
        int h2 = e / DQKP, d = e % DQKP;
        int h = h2 >> 1, c = h2 & 1;
        float qv = 0.f, kv = 0.f;
        if (d < 32) {
            qv = __half2float(qrow[h * 96 + c * 32 + d]);
            kv = __half2float(krow[h * 128 + c * 32 + d]);
        } else if (d < DQK) {
            int ee = d - 32;
            int f = ee >> 1;
            float q0 = __half2float(qrow[h * 96 + 64 + c * 16 + 2 * f]);
            float q1 = __half2float(qrow[h * 96 + 64 + c * 16 + 2 * f + 1]);
            float k0 = crow[KVCC + c * 16 + 2 * f];
            float k1 = crow[KVCC + c * 16 + 2 * f + 1];
            float C = cs[f], Sv = sn[f];
            if ((ee & 1) == 0) { qv = q0 * C - q1 * Sv; kv = k0 * C - k1 * Sv; }
            else               { qv = q0 * Sv + q1 * C; kv = k0 * Sv + k1 * C; }
        }
        Q[(long long)h2 * S_LEN * DQKP + (long long)i * DQKP + d] = __float2half_rn(qv);
        K[(long long)h2 * S_LEN * DQKP + (long long)i * DQKP + d] = __float2half_rn(kv);
    }
    for (int e = tid; e < NH * HD; e += 128) {
        int h = e >> 6, d = e & 63;
        V[(long long)h * S_LEN * HD + (long long)i * HD + d] = krow[h * 128 + 64 + d];
    }
}

// ---------- colmean stage 1: partial column sums over 128-row slabs ------------
__global__ void colmean_part_k(const __half* __restrict__ Ph, const float* __restrict__ invp,
                               float* __restrict__ gp)
{
    int j = blockIdx.x * blockDim.x + threadIdx.x;
    int h = blockIdx.y;
    int slab = blockIdx.z;
    if (j >= S_LEN) return;
    const __half* base = Ph + (long long)(2 * h) * S_LEN * S_LEN + j;
    const float*  iv   = invp + (2 * h) * S_LEN;
    int i0 = slab * 128;
    float s = 0.f;
#pragma unroll 4
    for (int i = i0; i < i0 + 128; i++)
        s += __half2float(base[(long long)i * S_LEN]) * iv[i];
    gp[((long long)slab * NH + h) * S_LEN + j] = s;
}
// ---------- colmean stage 2 (+ fused lambda scalar in block (0,0)) -------------
__global__ void colmean_red_k(const float* __restrict__ gp, float* __restrict__ g,
                              const float* __restrict__ q1, const float* __restrict__ k1,
                              const float* __restrict__ q2, const float* __restrict__ k2,
                              float* __restrict__ lamp)
{
    if (blockIdx.x == 0 && blockIdx.y == 0 && threadIdx.x < 32) {
        int t = threadIdx.x;
        float a = q1[t] * k1[t];
        float b = q2[t] * k2[t];
#pragma unroll
        for (int o = 16; o; o >>= 1) {
            a += __shfl_xor_sync(0xffffffffu, a, o);
            b += __shfl_xor_sync(0xffffffffu, b, o);
        }
        if (t == 0) *lamp = expf(a) - expf(b) + LAMBDA_INIT;
    }
    int j = blockIdx.x * blockDim.x + threadIdx.x;
    int h = blockIdx.y;
    if (j >= S_LEN) return;
    float s = 0.f;
#pragma unroll
    for (int slab = 0; slab < 12; slab++)
        s += gp[((long long)slab * NH + h) * S_LEN + j];
    g[h * S_LEN + j] = s;
}

// -------- per (token, head) rmsnorm: fp32 -> fp16, 4 rows per 256-thr CTA ------
__global__ __launch_bounds__(256)
void attn_norm_k(const float* __restrict__ ao, const float* __restrict__ w,
                 __half* __restrict__ outf)
{
    const int grpi = threadIdx.x >> 6;        // 0..3
    const int d    = threadIdx.x & 63;
    const int i    = blockIdx.x * 4 + grpi;
    const int h    = blockIdx.y;
    long long idx = ((long long)h * S_LEN + i) * HD + d;
    float v = ao[idx];
    float sq = v * v;
    __shared__ float sh[4][2];
#pragma unroll
    for (int o = 16; o; o >>= 1) sq += __shfl_xor_sync(0xffffffffu, sq, o);
    if ((d & 31) == 0) sh[grpi][d >> 5] = sq;
    __syncthreads();
    float tot = sh[grpi][0] + sh[grpi][1];
    outf[idx] = __float2half_rn(v * rsqrtf(tot / (float)HD + ATTN_EPS) * w[d]);
}

// ------------- merged weight conversion: 7 segments in one launch --------------
// segment 6 is the kv_down zero-pad (src == nullptr)
struct CvtSeg { const float* src; __half* dst; int n; };

__global__ void cvt_all_k(CvtSeg s0, CvtSeg s1, CvtSeg s2, CvtSeg s3,
                          CvtSeg s4, CvtSeg s5, CvtSeg s6)
{
    CvtSeg segs[7] = { s0, s1, s2, s3, s4, s5, s6 };
    long long total = 0;
#pragma unroll
    for (int k = 0; k < 7; k++) total += segs[k].n;

    long long i = ((long long)blockIdx.x * blockDim.x + threadIdx.x) * 4;
    long long stride = (long long)gridDim.x * blockDim.x * 4;
    for (; i < total; i += stride) {
        long long off = i;
        int seg = 0;
#pragma unroll
        for (int k = 0; k < 7; k++) {
            if (off < segs[k].n) { seg = k; break; }
            off -= segs[k].n;
        }
        __half* dst = segs[seg].dst + off;
        if (segs[seg].src) {
            float4 v = *(const float4*)(segs[seg].src + off);
            *(__half2*)(dst)     = __floats2half2_rn(v.x, v.y);
            *(__half2*)(dst + 2) = __floats2half2_rn(v.z, v.w);
        } else {
            *(__half2*)(dst)     = __floats2half2_rn(0.f, 0.f);
            *(__half2*)(dst + 2) = __floats2half2_rn(0.f, 0.f);
        }
    }
}

// ff_in conversion with swiglu row interleave
__global__ void cvt_swiglu_k(const float* __restrict__ in, __half* __restrict__ out)
{
    int i = (blockIdx.x * blockDim.x + threadIdx.x) * 4;
    int stride = gridDim.x * blockDim.x * 4;
    int n = 2 * DFF * DM;
    for (; i < n; i += stride) {
        int k = i / DM, d = i - k * DM;
        int orow = (k < DFF) ? (2 * k) : (2 * (k - DFF) + 1);
        float4 v = *(const float4*)(in + i);
        __half* dst = out + (long long)orow * DM + d;
        *(__half2*)(dst)     = __floats2half2_rn(v.x, v.y);
        *(__half2*)(dst + 2) = __floats2half2_rn(v.z, v.w);
    }
}

// ------------------------- host -------------------------
extern "C" void kernel_launch(void* const* d_in, const int* in_sizes, int n_in,
                              void* d_out, int out_size)
{
    const float* x    = (const float*)d_in[0];
    const float* fc   = (const float*)d_in[1];
    const float* fs   = (const float*)d_in[2];
    const float* n1w  = (const float*)d_in[3];
    const float* n2w  = (const float*)d_in[4];
    const float* kvdw = (const float*)d_in[5];
    const float* qdw  = (const float*)d_in[6];
    const float* kvnw = (const float*)d_in[7];
    const float* qnw  = (const float*)d_in[8];
    const float* kvuw = (const float*)d_in[9];
    const float* quw  = (const float*)d_in[10];
    const float* lq1  = (const float*)d_in[11];
    const float* lk1  = (const float*)d_in[12];
    const float* lq2  = (const float*)d_in[13];
    const float* lk2  = (const float*)d_in[14];
    const float* anw  = (const float*)d_in[15];
    const float* ow   = (const float*)d_in[16];
    const float* fiw  = (const float*)d_in[17];
    const float* fow  = (const float*)d_in[18];
    float* outp = (float*)d_out;

    __half *xin, *ckvn, *kvup, *cqn, *qf, *Q, *K, *V, *Ph, *af, *hb, *act;
    __half *kvdw_h, *qdw_h, *kvuw_h, *quw_h, *ow_h, *fiw_h, *fow_h;
    float *ckv, *cq, *gg, *gp, *ao, *x2, *lam, *invp;
    cudaGetSymbolAddress((void**)&xin,  g_xin);
    cudaGetSymbolAddress((void**)&ckv,  g_ckv);
    cudaGetSymbolAddress((void**)&ckvn, g_ckvn);
    cudaGetSymbolAddress((void**)&kvup, g_kvup);
    cudaGetSymbolAddress((void**)&cq,   g_cq);
    cudaGetSymbolAddress((void**)&cqn,  g_cqn);
    cudaGetSymbolAddress((void**)&qf,   g_qf);
    cudaGetSymbolAddress((void**)&Q,    g_Q);
    cudaGetSymbolAddress((void**)&K,    g_K);
    cudaGetSymbolAddress((void**)&V,    g_V);
    cudaGetSymbolAddress((void**)&Ph,   g_Ph);
    cudaGetSymbolAddress((void**)&invp, g_inv);
    cudaGetSymbolAddress((void**)&gg,   g_g);
    cudaGetSymbolAddress((void**)&gp,   g_gp);
    cudaGetSymbolAddress((void**)&ao,   g_ao);
    cudaGetSymbolAddress((void**)&af,   g_af);
    cudaGetSymbolAddress((void**)&x2,   g_x2);
    cudaGetSymbolAddress((void**)&hb,   g_hb);
    cudaGetSymbolAddress((void**)&act,  g_act);
    cudaGetSymbolAddress((void**)&lam,  g_lambda);
    cudaGetSymbolAddress((void**)&kvdw_h, g_kvdw_h);
    cudaGetSymbolAddress((void**)&qdw_h,  g_qdw_h);
    cudaGetSymbolAddress((void**)&kvuw_h, g_kvuw_h);
    cudaGetSymbolAddress((void**)&quw_h,  g_quw_h);
    cudaGetSymbolAddress((void**)&ow_h,   g_ow_h);
    cudaGetSymbolAddress((void**)&fiw_h,  g_fiw_h);
    cudaGetSymbolAddress((void**)&fow_h,  g_fow_h);

    static bool attr_set = false;
    if (!attr_set) {
        cudaFuncSetAttribute((const void*)hgemm<0,128>, cudaFuncAttributeMaxDynamicSharedMemorySize, SMEM_H128);
        cudaFuncSetAttribute((const void*)hgemm<1,128>, cudaFuncAttributeMaxDynamicSharedMemorySize, SMEM_H128);
        cudaFuncSetAttribute((const void*)hgemm<2,128>, cudaFuncAttributeMaxDynamicSharedMemorySize, SMEM_H128);
        cudaFuncSetAttribute((const void*)hgemm<0,64>,  cudaFuncAttributeMaxDynamicSharedMemorySize, SMEM_H64);
        cudaFuncSetAttribute((const void*)qk_softmax_k, cudaFuncAttributeMaxDynamicSharedMemorySize, QK_SMEM);
        attr_set = true;
    }

    auto grid128 = [](int M, int N, int batch) {
        return dim3((unsigned)(N / 128), (unsigned)(M / 128), (unsigned)batch);
    };
    auto grid64 = [](int M, int N, int batch) {
        return dim3((unsigned)(N / 64), (unsigned)(M / 128), (unsigned)batch);
    };

    // 0. weights -> fp16 in TWO launches: merged plain conversions + swiglu interleave
    {
        CvtSeg s0 = { kvdw, kvdw_h,              288 * DM };
        CvtSeg s1 = { nullptr, kvdw_h + 288 * DM, 96 * DM };   // zero-pad
        CvtSeg s2 = { qdw,  qdw_h,  QCC * DM };
        CvtSeg s3 = { kvuw, kvuw_h, 2048 * KVCC };
        CvtSeg s4 = { quw,  quw_h,  1536 * QCC };
        CvtSeg s5 = { ow,   ow_h,   DM * DM };
        CvtSeg s6 = { fow,  fow_h,  DM * DFF };
        cvt_all_k<<<2368, 256>>>(s0, s1, s2, s3, s4, s5, s6);
    }
    cvt_swiglu_k<<<4096, 256>>>(fiw, fiw_h);

    // 1. xin = rmsnorm(x) -> fp16
    rmsnorm_h<<<S_LEN, 256>>>(x, n1w, xin, DM, DM, DM, EPS_RMS);
    // 2. ckv = xin @ kv_down^T [1536, 384(pad)] fp32  (N64: 72 CTAs)
    hgemm<0,64><<<grid64(S_LEN, 384, 1), 256, SMEM_H64>>>(xin, kvdw_h, nullptr, ckv,
        S_LEN, 384, DM, 0, 0, 0, 1.f);
    // 3. ckvn = rmsnorm(ckv[:, :256]) -> fp16
    rmsnorm_h<<<S_LEN, 256>>>(ckv, kvnw, ckvn, KVCC, 384, KVCC, EPS_RMS);
    // 4. kvup = ckvn @ kv_up^T [1536, 2048] fp16  (N128: 192 CTAs)
    hgemm<1,128><<<grid128(S_LEN, 2048, 1), 256, SMEM_H128>>>(ckvn, kvuw_h, nullptr, kvup,
        S_LEN, 2048, KVCC, 0, 0, 0, 1.f);
    // 5. cq = xin @ q_down^T [1536, 384] fp32  (N64: 72 CTAs)
    hgemm<0,64><<<grid64(S_LEN, QCC, 1), 256, SMEM_H64>>>(xin, qdw_h, nullptr, cq,
        S_LEN, QCC, DM, 0, 0, 0, 1.f);
    // 6. cqn = rmsnorm(cq) -> fp16
    rmsnorm_h<<<S_LEN, 256>>>(cq, qnw, cqn, QCC, QCC, QCC, EPS_RMS);
    // 7. qf = cqn @ q_up^T [1536, 1536] fp16  (N128: 144 CTAs)
    hgemm<1,128><<<grid128(S_LEN, 1536, 1), 256, SMEM_H128>>>(cqn, quw_h, nullptr, qf,
        S_LEN, 1536, QCC, 0, 0, 0, 1.f);
    // 8. build Q/K/V (fp16, Q/K padded to 64)
    build_qkv_k<<<S_LEN, 128>>>(qf, kvup, ckv, fc, fs, Q, K, V);
    // 9. fused QK^T + masked unnormalized softmax
    qk_softmax_k<<<dim3(S_LEN / 128, H2), 256, QK_SMEM>>>(Q, K, Ph, invp);
    // 10. column sums (two-stage deterministic; stage 2 also computes lambda)
    colmean_part_k<<<dim3((S_LEN + 255) / 256, NH, 12), 256>>>(Ph, invp, gp);
    colmean_red_k<<<dim3((S_LEN + 255) / 256, NH), 256>>>(gp, gg, lq1, lk1, lq2, lk2, lam);
    // 11+12. fused combine + AV (K-tile 64)
    av_k<<<dim3(S_LEN / AVM, NH), 256>>>(Ph, invp, V, gg, lam, ao);
    // 13. attn rmsnorm -> fp16 (4 rows per CTA)
    attn_norm_k<<<dim3(S_LEN / 4, NH), 256>>>(ao, anw, af);
    // 14. x2 = x + af @ o_w^T fp32  (N128: 96 CTAs)
    hgemm<0,128><<<grid128(S_LEN, DM, 1), 256, SMEM_H128>>>(af, ow_h, x, x2,
        S_LEN, DM, DM, 0, 0, 0, 1.f);
    // 15. hb = rmsnorm(x2) -> fp16
    rmsnorm_h<<<S_LEN, 256>>>(x2, n2w, hb, DM, DM, DM, EPS_RMS);
    // 16. act = swiglu(hb @ ff_in^T) [1536, 4096] fp16  (N128: 768 CTAs)
    hgemm<2,128><<<grid128(S_LEN, 2 * DFF, 1), 256, SMEM_H128>>>(hb, fiw_h, nullptr, act,
        S_LEN, 2 * DFF, DM, 0, 0, 0, 1.f);
    // 17. out = x2 + act @ ff_out^T fp32  (N128: 96 CTAs)
    hgemm<0,128><<<grid128(S_LEN, DM, 1), 256, SMEM_H128>>>(act, fow_h, x2, outp,
        S_LEN, DM, DFF, 0, 0, 0, 1.f);
}

// round 17
// speedup vs baseline: 1.0962x; 1.0335x over previous
#include <cuda_runtime.h>
#include <cuda_fp16.h>
#include <math.h>
#include <stdint.h>

#define S_LEN 1536
#define DM    1024
#define NH    16
#define HD    64
#define H2    32
#define DQK   48
#define DQKP  64
#define KVCC  256
#define ROPE_ 32
#define QCC   384
#define DFF   4096
#define SPP   384
#define EPS_RMS 1.1920929e-07f
#define ATTN_EPS 1e-5f
#define SCALING 0.14433756729740643f
#define LAMBDA_INIT 0.2f

// ------------------------- device scratch -------------------------
__device__ __half g_xin [S_LEN * DM];
__device__ float  g_cqkv[S_LEN * 768];                   // [ckv(384 pad) | cq(384)]
__device__ __half g_ckvn[S_LEN * KVCC];
__device__ __half g_kvup[S_LEN * 2048];
__device__ __half g_cqn [S_LEN * QCC];
__device__ __half g_qf  [S_LEN * 1536];
__device__ __half g_Q   [(size_t)H2 * S_LEN * DQKP];
__device__ __half g_K   [(size_t)H2 * S_LEN * DQKP];
__device__ __half g_V   [(size_t)NH * S_LEN * HD];
__device__ __half g_Ph  [(size_t)H2 * S_LEN * S_LEN];   // UNNORMALIZED exp, fp16
__device__ float  g_inv [H2 * S_LEN];                    // per-row 1/sum
__device__ float  g_g   [NH * S_LEN];
__device__ float  g_gp  [12 * NH * S_LEN];               // colmean partials
__device__ float  g_ao  [(size_t)NH * S_LEN * HD];
__device__ __half g_af  [S_LEN * DM];
__device__ float  g_x2  [S_LEN * DM];
__device__ __half g_hb  [S_LEN * DM];
__device__ __half g_act [(size_t)S_LEN * DFF];
__device__ float  g_lambda;
// fp16 weight copies
__device__ __half g_wqd_h [768 * DM];                    // [kv_down(384 pad) | q_down(384)]
__device__ __half g_kvuw_h[2048 * KVCC];
__device__ __half g_quw_h [1536 * QCC];
__device__ __half g_ow_h  [(size_t)DM * DM];
__device__ __half g_fiw_h [(size_t)2 * DFF * DM];       // swiglu-interleaved rows
__device__ __half g_fow_h [(size_t)DM * DFF];

// ------------------------- helpers -------------------------
__device__ __forceinline__ void cpa16(void* smem_dst, const void* gsrc) {
    unsigned a = (unsigned)__cvta_generic_to_shared(smem_dst);
    asm volatile("cp.async.ca.shared.global [%0], [%1], 16;\n" :: "r"(a), "l"(gsrc));
}
__device__ __forceinline__ void cpa_commit() { asm volatile("cp.async.commit_group;\n"); }
template <int NG>
__device__ __forceinline__ void cpa_wait() { asm volatile("cp.async.wait_group %0;\n" :: "n"(NG)); }

#define LDM_X4(a0,a1,a2,a3,p) \
    asm volatile("ldmatrix.sync.aligned.m8n8.x4.shared.b16 {%0,%1,%2,%3}, [%4];" \
        : "=r"(a0), "=r"(a1), "=r"(a2), "=r"(a3) \
        : "r"((unsigned)__cvta_generic_to_shared(p)))
#define LDM_X2(b0,b1,p) \
    asm volatile("ldmatrix.sync.aligned.m8n8.x2.shared.b16 {%0,%1}, [%2];" \
        : "=r"(b0), "=r"(b1) \
        : "r"((unsigned)__cvta_generic_to_shared(p)))
#define LDM_X2T(b0,b1,p) \
    asm volatile("ldmatrix.sync.aligned.m8n8.x2.trans.shared.b16 {%0,%1}, [%2];" \
        : "=r"(b0), "=r"(b1) \
        : "r"((unsigned)__cvta_generic_to_shared(p)))
#define MMA_F16(d, a, b) \
    asm volatile( \
        "mma.sync.aligned.m16n8k16.row.col.f32.f16.f16.f32 " \
        "{%0,%1,%2,%3}, {%4,%5,%6,%7}, {%8,%9}, {%0,%1,%2,%3};" \
        : "+f"(d[0]), "+f"(d[1]), "+f"(d[2]), "+f"(d[3]) \
        : "r"(a[0]), "r"(a[1]), "r"(a[2]), "r"(a[3]), "r"(b[0]), "r"(b[1]))

#define KSTR 72     /* stride (halves) for 64-wide k-tiles */

// --------- FP16 GEMM: 128xNT tiles (NT=128 or 64), K-tile=64, 2-stage ----------
// MODE: 0 = fp32 out (+Res), 1 = fp16 out, 2 = swiglu fp16 out (paired cols)
#define SMEM_H128 (2 * (128 + 128) * KSTR * 2)
#define SMEM_H64  (2 * (128 + 64)  * KSTR * 2)

template <int MODE, int NT>
__global__ __launch_bounds__(256, 2)
void hgemm(const __half* __restrict__ A, const __half* __restrict__ B,
           const float* __restrict__ Res, void* __restrict__ Cv,
           int M, int N, int K, long long sA, long long sB, long long sC,
           float scale)
{
    constexpr int WN  = NT / 32;
    constexpr int WMT = (8 / WN) == 2 ? 4 : 2;
    constexpr int BCH = NT / 32;

    extern __shared__ __half hsm[];
    __half* AsB = hsm;
    __half* BsB = hsm + 2 * 128 * KSTR;

    A += (long long)blockIdx.z * sA;
    B += (long long)blockIdx.z * sB;
    float*  Cf = (float*)Cv  + (long long)blockIdx.z * sC;
    __half* Ch = (__half*)Cv + (long long)blockIdx.z * sC;

    const int tid  = threadIdx.x;
    const int lane = tid & 31;
    const int warp = tid >> 5;
    const int wm   = warp / WN;
    const int wn   = warp % WN;
    const int row0 = blockIdx.y * 128;
    const int col0 = blockIdx.x * NT;
    const int grp  = lane >> 2;
    const int tig  = lane & 3;

    const int nk = K / 64;

    auto load_tiles = [&](int ki, int buf) {
        const __half* Ag = A + (long long)row0 * K + ki * 64;
        __half* Ad = AsB + buf * 128 * KSTR;
#pragma unroll
        for (int it = 0; it < 4; it++) {
            int f = tid + it * 256;
            int r = f >> 3, c8 = (f & 7) * 8;
            cpa16(Ad + r * KSTR + c8, Ag + (long long)r * K + c8);
        }
        const __half* Bg = B + (long long)col0 * K + ki * 64;
        __half* Bd = BsB + buf * NT * KSTR;
#pragma unroll
        for (int it = 0; it < BCH; it++) {
            int f = tid + it * 256;
            int r = f >> 3, c8 = (f & 7) * 8;
            cpa16(Bd + r * KSTR + c8, Bg + (long long)r * K + c8);
        }
        cpa_commit();
    };

    float acc[WMT][4][4];
#pragma unroll
    for (int i = 0; i < WMT; i++)
#pragma unroll
        for (int j = 0; j < 4; j++)
#pragma unroll
            for (int l = 0; l < 4; l++) acc[i][j][l] = 0.f;

    load_tiles(0, 0);

    const int arow = (lane & 15);
    const int asel = (lane >> 4) * 8;
    const int brow = (lane & 7);
    const int bsel = ((lane >> 3) & 1) * 8;

    for (int i = 0; i < nk; i++) {
        int cur = i & 1;
        cpa_wait<0>();
        __syncthreads();
        if (i + 1 < nk) load_tiles(i + 1, cur ^ 1);

        const __half* Ab = AsB + cur * 128 * KSTR;
        const __half* Bb = BsB + cur * NT * KSTR;
#pragma unroll
        for (int kc = 0; kc < 4; kc++) {
            unsigned a[WMT][4], b[4][2];
            int acol = kc * 16 + asel;
            int bcol = kc * 16 + bsel;
#pragma unroll
            for (int mi = 0; mi < WMT; mi++) {
                const __half* p = Ab + (wm * (WMT * 16) + mi * 16 + arow) * KSTR + acol;
                LDM_X4(a[mi][0], a[mi][1], a[mi][2], a[mi][3], p);
            }
#pragma unroll
            for (int ni = 0; ni < 4; ni++) {
                const __half* p = Bb + (wn * 32 + ni * 8 + brow) * KSTR + bcol;
                LDM_X2(b[ni][0], b[ni][1], p);
            }
#pragma unroll
            for (int mi = 0; mi < WMT; mi++)
#pragma unroll
                for (int ni = 0; ni < 4; ni++)
                    MMA_F16(acc[mi][ni], a[mi], b[ni]);
        }
    }

#pragma unroll
    for (int mi = 0; mi < WMT; mi++)
#pragma unroll
        for (int ni = 0; ni < 4; ni++)
#pragma unroll
            for (int h = 0; h < 2; h++) {
                int r = row0 + wm * (WMT * 16) + mi * 16 + grp + h * 8;
                int cc = col0 + wn * 32 + ni * 8 + tig * 2;
                float v0 = acc[mi][ni][h * 2 + 0] * scale;
                float v1 = acc[mi][ni][h * 2 + 1] * scale;
                if (MODE == 2) {
                    float o = v0 * (v1 / (1.f + __expf(-v1)));
                    Ch[(long long)r * DFF + (cc >> 1)] = __float2half_rn(o);
                } else if (MODE == 1) {
                    *(__half2*)(Ch + (long long)r * N + cc) = __floats2half2_rn(v0, v1);
                } else {
                    long long o = (long long)r * N + cc;
                    if (Res) { v0 += Res[o]; v1 += Res[o + 1]; }
                    Cf[o] = v0; Cf[o + 1] = v1;
                }
            }
}

// --------- fused QK^T + masked unnormalized softmax (64-wide j-tiles) ----------
#define QKS 72
#define QK_SMEM (128*QKS*2 + 2*64*QKS*2 + 128*QKS*2)

__global__ __launch_bounds__(256)
void qk_softmax_k(const __half* __restrict__ Q, const __half* __restrict__ Kg,
                  __half* __restrict__ Ph, float* __restrict__ invp)
{
    extern __shared__ char qsm[];
    __half* Qs = (__half*)qsm;
    __half* Ks = Qs + 128 * QKS;
    __half* Os = Ks + 2 * 64 * QKS;

    const int h2   = blockIdx.y;
    const int row0 = blockIdx.x * 128;
    const int tid  = threadIdx.x;
    const int lane = tid & 31;
    const int warp = tid >> 5;
    const int grp  = lane >> 2;
    const int tig  = lane & 3;

    const __half* Qh = Q + (long long)h2 * S_LEN * DQKP;
    const __half* Kh = Kg + (long long)h2 * S_LEN * DQKP;
    __half* Pout = Ph + (long long)h2 * S_LEN * S_LEN;

#pragma unroll
    for (int it = 0; it < 4; it++) {
        int f = tid + it * 256, r = f >> 3, c8 = (f & 7) * 8;
        cpa16(Qs + r * QKS + c8, Qh + (long long)(row0 + r) * DQKP + c8);
    }
    cpa_commit();

    auto loadK = [&](int jt, int buf) {
#pragma unroll
        for (int it = 0; it < 2; it++) {
            int f = tid + it * 256, r = f >> 3, c8 = (f & 7) * 8;
            cpa16(Ks + buf * 64 * QKS + r * QKS + c8,
                  Kh + (long long)(jt * 64 + r) * DQKP + c8);
        }
        cpa_commit();
    };

    const int r0  = warp * 16 + grp;
    const int ip0 = (row0 + r0) % SPP;
    const int ip1 = (row0 + r0 + 8) % SPP;

    float s0 = 0.f, s1 = 0.f;

    loadK(0, 0);

    const int NJT = S_LEN / 64;
    for (int jt = 0; jt < NJT; jt++) {
        int buf = jt & 1;
        if (jt + 1 < NJT) { loadK(jt + 1, buf ^ 1); cpa_wait<1>(); }
        else              { cpa_wait<0>(); }
        __syncthreads();

        float acc[8][4];
#pragma unroll
        for (int ni = 0; ni < 8; ni++)
#pragma unroll
            for (int l = 0; l < 4; l++) acc[ni][l] = 0.f;

        const __half* Kb = Ks + buf * 64 * QKS;
#pragma unroll
        for (int kc = 0; kc < 4; kc++) {
            unsigned a[4];
            const __half* pa = Qs + (warp * 16 + (lane & 15)) * QKS
                                  + kc * 16 + (lane >> 4) * 8;
            LDM_X4(a[0], a[1], a[2], a[3], pa);
#pragma unroll
            for (int ni = 0; ni < 8; ni++) {
                unsigned bb[2];
                const __half* pb = Kb + (ni * 8 + (lane & 7)) * QKS
                                      + kc * 16 + ((lane >> 3) & 1) * 8;
                LDM_X2(bb[0], bb[1], pb);
                MMA_F16(acc[ni], a, bb);
            }
        }

#pragma unroll
        for (int ni = 0; ni < 8; ni++) {
            int c0  = jt * 64 + ni * 8 + tig * 2;
            int jm0 = c0 % SPP;
            float e00 = (jm0     <= ip0) ? __expf(fminf(acc[ni][0] * SCALING, 10.f)) : 0.f;
            float e01 = (jm0 + 1 <= ip0) ? __expf(fminf(acc[ni][1] * SCALING, 10.f)) : 0.f;
            float e10 = (jm0     <= ip1) ? __expf(fminf(acc[ni][2] * SCALING, 10.f)) : 0.f;
            float e11 = (jm0 + 1 <= ip1) ? __expf(fminf(acc[ni][3] * SCALING, 10.f)) : 0.f;
            s0 += e00 + e01;
            s1 += e10 + e11;
            *(__half2*)(Os + r0 * QKS + ni * 8 + tig * 2)       = __floats2half2_rn(e00, e01);
            *(__half2*)(Os + (r0 + 8) * QKS + ni * 8 + tig * 2) = __floats2half2_rn(e10, e11);
        }
        __syncthreads();

#pragma unroll
        for (int it = 0; it < 4; it++) {
            int f = tid + it * 256, r = f >> 3, c8 = (f & 7) * 8;
            uint4 u = *(uint4*)(Os + r * QKS + c8);
            *(uint4*)(Pout + (long long)(row0 + r) * S_LEN + jt * 64 + c8) = u;
        }
        __syncthreads();
    }

#pragma unroll
    for (int x = 1; x <= 2; x <<= 1) {
        s0 += __shfl_xor_sync(0xffffffffu, s0, x);
        s1 += __shfl_xor_sync(0xffffffffu, s1, x);
    }
    if (tig == 0) {
        invp[h2 * S_LEN + row0 + r0]     = 1.f / s0;
        invp[h2 * S_LEN + row0 + r0 + 8] = 1.f / s1;
    }
}

// --------------- fused differential-combine + AV GEMM, K-tile 64 ---------------
#define AVM 64

__global__ __launch_bounds__(256)
void av_k(const __half* __restrict__ Ph, const float* __restrict__ invp,
          const __half* __restrict__ V,
          const float* __restrict__ g, const float* __restrict__ lamp,
          float* __restrict__ O)
{
    __shared__ __half As[AVM * KSTR];
    __shared__ __half Bs[64 * KSTR];
    __shared__ float  sI1[AVM], sI2[AVM];

    const int h    = blockIdx.y;
    const int row0 = blockIdx.x * AVM;
    const int tid  = threadIdx.x;
    const int lane = tid & 31;
    const int warp = tid >> 5;
    const int wm   = warp >> 1;
    const int wn   = warp & 1;
    const int grp  = lane >> 2;
    const int tig  = lane & 3;

    const float lam = *lamp;
    const float gl  = lam * (1.f / (float)S_LEN);
    const __half* p1 = Ph + (long long)(2 * h) * S_LEN * S_LEN;
    const __half* p2 = Ph + (long long)(2 * h + 1) * S_LEN * S_LEN;
    const __half* Vh = V + (long long)h * S_LEN * HD;
    const float*  gh = g + h * S_LEN;

    if (tid < AVM) {
        sI1[tid] = invp[(2 * h) * S_LEN + row0 + tid];
        sI2[tid] = invp[(2 * h + 1) * S_LEN + row0 + tid];
    }
    __syncthreads();

    float acc[4][4];
#pragma unroll
    for (int j = 0; j < 4; j++)
#pragma unroll
        for (int l = 0; l < 4; l++) acc[j][l] = 0.f;

    for (int j0 = 0; j0 < S_LEN; j0 += 64) {
#pragma unroll
        for (int it = 0; it < 2; it++) {
            int f = tid + it * 256;
            int kk = f >> 3, c8 = (f & 7) * 8;
            cpa16(Bs + kk * KSTR + c8, Vh + (long long)(j0 + kk) * HD + c8);
        }
        cpa_commit();

#pragma unroll
        for (int it = 0; it < 2; it++) {
            int f = tid + it * 256;
            int r = f >> 3, c8 = (f & 7) * 8;
            int ip = (row0 + r) % SPP;
            float i1 = sI1[r], i2 = sI2[r];
            long long off = (long long)(row0 + r) * S_LEN + j0 + c8;
            uint4 u1 = *(const uint4*)(p1 + off);
            uint4 u2 = *(const uint4*)(p2 + off);
            const __half2* h1 = (const __half2*)&u1;
            const __half2* h2 = (const __half2*)&u2;
            __half outh[8];
            int jb = j0 + c8;
#pragma unroll
            for (int e = 0; e < 4; e++) {
                float2 f1 = __half22float2(h1[e]);
                float2 f2 = __half22float2(h2[e]);
                int ja = jb + 2 * e, jbb = ja + 1;
                float o0 = ((ja  % SPP) > ip) ? 0.f
                           : (f1.x * i1 - lam * (f2.x * i2) + gl * gh[ja]);
                float o1 = ((jbb % SPP) > ip) ? 0.f
                           : (f1.y * i1 - lam * (f2.y * i2) + gl * gh[jbb]);
                outh[2 * e]     = __float2half_rn(o0);
                outh[2 * e + 1] = __float2half_rn(o1);
            }
            *(uint4*)(As + r * KSTR + c8) = *(uint4*)outh;
        }
        cpa_wait<0>();
        __syncthreads();

#pragma unroll
        for (int kc = 0; kc < 4; kc++) {
            unsigned a[4], b[4][2];
            {
                const __half* p = As + (wm * 16 + (lane & 15)) * KSTR
                                     + kc * 16 + (lane >> 4) * 8;
                LDM_X4(a[0], a[1], a[2], a[3], p);
            }
#pragma unroll
            for (int ni = 0; ni < 4; ni++) {
                int krow = kc * 16 + ((lane >> 3) & 1) * 8 + (lane & 7);
                int ncol = wn * 32 + ni * 8;
                const __half* p = Bs + krow * KSTR + ncol;
                LDM_X2T(b[ni][0], b[ni][1], p);
            }
#pragma unroll
            for (int ni = 0; ni < 4; ni++)
                MMA_F16(acc[ni], a, b[ni]);
        }
        __syncthreads();
    }

#pragma unroll
    for (int ni = 0; ni < 4; ni++)
#pragma unroll
        for (int hh = 0; hh < 2; hh++) {
            int r = row0 + wm * 16 + grp + hh * 8;
            int cc = wn * 32 + ni * 8 + tig * 2;
            long long o = ((long long)h * S_LEN + r) * HD + cc;
            O[o]     = acc[ni][hh * 2 + 0];
            O[o + 1] = acc[ni][hh * 2 + 1];
        }
}

// ------------------------- rmsnorm: fp32 in -> fp16 out -------------------------
__global__ void rmsnorm_h(const float* __restrict__ in, const float* __restrict__ w,
                          __half* __restrict__ out, int cols, int in_ld, int out_ld,
                          float eps)
{
    const long long row = blockIdx.x;
    const float* ip = in + row * in_ld;
    __half* op = out + row * out_ld;

    float ss = 0.f;
    for (int j = threadIdx.x; j < cols; j += blockDim.x) {
        float v = ip[j];
        ss += v * v;
    }
    __shared__ float sh[32];
    int lane = threadIdx.x & 31, wid = threadIdx.x >> 5;
#pragma unroll
    for (int o = 16; o; o >>= 1) ss += __shfl_xor_sync(0xffffffffu, ss, o);
    if (lane == 0) sh[wid] = ss;
    __syncthreads();
    int nw = (blockDim.x + 31) >> 5;
    float tot = 0.f;
    if (threadIdx.x < nw) tot = sh[threadIdx.x];
    if (wid == 0) {
#pragma unroll
        for (int o = 16; o; o >>= 1) tot += __shfl_xor_sync(0xffffffffu, tot, o);
        if (lane == 0) sh[0] = tot;
    }
    __syncthreads();
    float inv = rsqrtf(sh[0] / (float)cols + eps);
    for (int j = threadIdx.x; j < cols; j += blockDim.x)
        op[j] = __float2half_rn(ip[j] * inv * w[j]);
}

// ----- dual rmsnorm from combined cqkv buffer: y=0 -> ckvn(256), y=1 -> cqn(384) -
__global__ void rmsnorm_dual_h(const float* __restrict__ cqkv,
                               const float* __restrict__ kvnw,
                               const float* __restrict__ qnw,
                               __half* __restrict__ ckvn, __half* __restrict__ cqn)
{
    const long long row = blockIdx.x;
    const int which = blockIdx.y;
    const float* ip = cqkv + row * 768 + (which ? 384 : 0);
    const float* w  = which ? qnw : kvnw;
    __half* op      = which ? (cqn + row * QCC) : (ckvn + row * KVCC);
    const int cols  = which ? QCC : KVCC;

    float ss = 0.f;
    for (int j = threadIdx.x; j < cols; j += blockDim.x) {
        float v = ip[j];
        ss += v * v;
    }
    __shared__ float sh[32];
    int lane = threadIdx.x & 31, wid = threadIdx.x >> 5;
#pragma unroll
    for (int o = 16; o; o >>= 1) ss += __shfl_xor_sync(0xffffffffu, ss, o);
    if (lane == 0) sh[wid] = ss;
    __syncthreads();
    int nw = (blockDim.x + 31) >> 5;
    float tot = 0.f;
    if (threadIdx.x < nw) tot = sh[threadIdx.x];
    if (wid == 0) {
#pragma unroll
        for (int o = 16; o; o >>= 1) tot += __shfl_xor_sync(0xffffffffu, tot, o);
        if (lane == 0) sh[0] = tot;
    }
    __syncthreads();
    float inv = rsqrtf(sh[0] / (float)cols + EPS_RMS);
    for (int j = threadIdx.x; j < cols; j += blockDim.x)
        op[j] = __float2half_rn(ip[j] * inv * w[j]);
}

// ------------------------- build Q/K/V with RoPE (fp16 out) --------------------
__global__ void build_qkv_k(const __half* __restrict__ qf, const __half* __restrict__ kvup,
                            const float* __restrict__ cqkv,
                            const float* __restrict__ fcos, const float* __restrict__ fsin,
                            __half* __restrict__ Q, __half* __restrict__ K,
                            __half* __restrict__ V)
{
    const int i = blockIdx.x;
    const int tid = threadIdx.x;              // 128
    __shared__ float cs[8], sn[8];
    int p = i >> 2;
    if (tid < 8) {
        if (p == 0) { cs[tid] = 1.f; sn[tid] = 0.f; }
        else { cs[tid] = fcos[(p - 1) * 8 + tid]; sn[tid] = fsin[(p - 1) * 8 + tid]; }
    }
    __syncthreads();

    const __half* qrow = qf + (long long)i * 1536;
    const __half* krow = kvup + (long long)i * 2048;
    const float*  crow = cqkv + (long long)i * 768;   // k_rope at cols 256..287

    for (int e = tid; e < H2 * DQKP; e += 128) {
        int h2 = e / DQKP, d = e % DQKP;
        int h = h2 >> 1, c = h2 & 1;
        float qv = 0.f, kv = 0.f;
        if (d < 32) {
            qv = __half2float(qrow[h * 96 + c * 32 + d]);
            kv = __half2float(krow[h * 128 + c * 32 + d]);
        } else if (d < DQK) {
            int ee = d - 32;
            int f = ee >> 1;
            float q0 = __half2float(qrow[h * 96 + 64 + c * 16 + 2 * f]);
            float q1 = __half2float(qrow[h * 96 + 64 + c * 16 + 2 * f + 1]);
            float k0 = crow[KVCC + c * 16 + 2 * f];
            float k1 = crow[KVCC + c * 16 + 2 * f + 1];
            float C = cs[f], Sv = sn[f];
            if ((ee & 1) == 0) { qv = q0 * C - q1 * Sv; kv = k0 * C - k1 * Sv; }
            else               { qv = q0 * Sv + q1 * C; kv = k0 * Sv + k1 * C; }
        }
        Q[(long long)h2 * S_LEN * DQKP + (long long)i * DQKP + d] = __float2half_rn(qv);
        K[(long long)h2 * S_LEN * DQKP + (long long)i * DQKP + d] = __float2half_rn(kv);
    }
    for (int e = tid; e < NH * HD; e += 128) {
        int h = e >> 6, d = e & 63;
        V[(long long)h * S_LEN * HD + (long long)i * HD + d] = krow[h * 128 + 64 + d];
    }
}

// ---------- colmean stage 1: partial column sums over 128-row slabs ------------
__global__ void colmean_part_k(const __half* __restrict__ Ph, const float* __restrict__ invp,
                               float* __restrict__ gp)
{
    int j = blockIdx.x * blockDim.x + threadIdx.x;
    int h = blockIdx.y;
    int slab = blockIdx.z;
    if (j >= S_LEN) return;
    const __half* base = Ph + (long long)(2 * h) * S_LEN * S_LEN + j;
    const float*  iv   = invp + (2 * h) * S_LEN;
    int i0 = slab * 128;
    float s = 0.f;
#pragma unroll 4
    for (int i = i0; i < i0 + 128; i++)
        s += __half2float(base[(long long)i * S_LEN]) * iv[i];
    gp[((long long)slab * NH + h) * S_LEN + j] = s;
}
// ---------- colmean stage 2 (+ fused lambda scalar in block (0,0)) -------------
__global__ void colmean_red_k(const float* __restrict__ gp, float* __restrict__ g,
                              const float* __restrict__ q1, const float* __restrict__ k1,
                              const float* __restrict__ q2, const float* __restrict__ k2,
                              float* __restrict__ lamp)
{
    if (blockIdx.x == 0 && blockIdx.y == 0 && threadIdx.x < 32) {
        int t = threadIdx.x;
        float a = q1[t] * k1[t];
        float b = q2[t] * k2[t];
#pragma unroll
        for (int o = 16; o; o >>= 1) {
            a += __shfl_xor_sync(0xffffffffu, a, o);
            b += __shfl_xor_sync(0xffffffffu, b, o);
        }
        if (t == 0) *lamp = expf(a) - expf(b) + LAMBDA_INIT;
    }
    int j = blockIdx.x * blockDim.x + threadIdx.x;
    int h = blockIdx.y;
    if (j >= S_LEN) return;
    float s = 0.f;
#pragma unroll
    for (int slab = 0; slab < 12; slab++)
        s += gp[((long long)slab * NH + h) * S_LEN + j];
    g[h * S_LEN + j] = s;
}

// -------- per (token, head) rmsnorm: fp32 -> fp16, 4 rows per 256-thr CTA ------
__global__ __launch_bounds__(256)
void attn_norm_k(const float* __restrict__ ao, const float* __restrict__ w,
                 __half* __restrict__ outf)
{
    const int grpi = threadIdx.x >> 6;
    const int d    = threadIdx.x & 63;
    const int i    = blockIdx.x * 4 + grpi;
    const int h    = blockIdx.y;
    long long idx = ((long long)h * S_LEN + i) * HD + d;
    float v = ao[idx];
    float sq = v * v;
    __shared__ float sh[4][2];
#pragma unroll
    for (int o = 16; o; o >>= 1) sq += __shfl_xor_sync(0xffffffffu, sq, o);
    if ((d & 31) == 0) sh[grpi][d >> 5] = sq;
    __syncthreads();
    float tot = sh[grpi][0] + sh[grpi][1];
    outf[idx] = __float2half_rn(v * rsqrtf(tot / (float)HD + ATTN_EPS) * w[d]);
}

// ------------- merged weight conversion: 7 segments in one launch --------------
struct CvtSeg { const float* src; __half* dst; int n; };

__global__ void cvt_all_k(CvtSeg s0, CvtSeg s1, CvtSeg s2, CvtSeg s3,
                          CvtSeg s4, CvtSeg s5, CvtSeg s6)
{
    CvtSeg segs[7] = { s0, s1, s2, s3, s4, s5, s6 };
    long long total = 0;
#pragma unroll
    for (int k = 0; k < 7; k++) total += segs[k].n;

    long long i = ((long long)blockIdx.x * blockDim.x + threadIdx.x) * 4;
    long long stride = (long long)gridDim.x * blockDim.x * 4;
    for (; i < total; i += stride) {
        long long off = i;
        int seg = 0;
#pragma unroll
        for (int k = 0; k < 7; k++) {
            if (off < segs[k].n) { seg = k; break; }
            off -= segs[k].n;
        }
        __half* dst = segs[seg].dst + off;
        if (segs[seg].src) {
            float4 v = *(const float4*)(segs[seg].src + off);
            *(__half2*)(dst)     = __floats2half2_rn(v.x, v.y);
            *(__half2*)(dst + 2) = __floats2half2_rn(v.z, v.w);
        } else {
            *(__half2*)(dst)     = __floats2half2_rn(0.f, 0.f);
            *(__half2*)(dst + 2) = __floats2half2_rn(0.f, 0.f);
        }
    }
}

// ff_in conversion with swiglu row interleave
__global__ void cvt_swiglu_k(const float* __restrict__ in, __half* __restrict__ out)
{
    int i = (blockIdx.x * blockDim.x + threadIdx.x) * 4;
    int stride = gridDim.x * blockDim.x * 4;
    int n = 2 * DFF * DM;
    for (; i < n; i += stride) {
        int k = i / DM, d = i - k * DM;
        int orow = (k < DFF) ? (2 * k) : (2 * (k - DFF) + 1);
        float4 v = *(const float4*)(in + i);
        __half* dst = out + (long long)orow * DM + d;
        *(__half2*)(dst)     = __floats2half2_rn(v.x, v.y);
        *(__half2*)(dst + 2) = __floats2half2_rn(v.z, v.w);
    }
}

// ------------------------- host -------------------------
extern "C" void kernel_launch(void* const* d_in, const int* in_sizes, int n_in,
                              void* d_out, int out_size)
{
    const float* x    = (const float*)d_in[0];
    const float* fc   = (const float*)d_in[1];
    const float* fs   = (const float*)d_in[2];
    const float* n1w  = (const float*)d_in[3];
    const float* n2w  = (const float*)d_in[4];
    const float* kvdw = (const float*)d_in[5];
    const float* qdw  = (const float*)d_in[6];
    const float* kvnw = (const float*)d_in[7];
    const float* qnw  = (const float*)d_in[8];
    const float* kvuw = (const float*)d_in[9];
    const float* quw  = (const float*)d_in[10];
    const float* lq1  = (const float*)d_in[11];
    const float* lk1  = (const float*)d_in[12];
    const float* lq2  = (const float*)d_in[13];
    const float* lk2  = (const float*)d_in[14];
    const float* anw  = (const float*)d_in[15];
    const float* ow   = (const float*)d_in[16];
    const float* fiw  = (const float*)d_in[17];
    const float* fow  = (const float*)d_in[18];
    float* outp = (float*)d_out;

    __half *xin, *ckvn, *kvup, *cqn, *qf, *Q, *K, *V, *Ph, *af, *hb, *act;
    __half *wqd_h, *kvuw_h, *quw_h, *ow_h, *fiw_h, *fow_h;
    float *cqkv, *gg, *gp, *ao, *x2, *lam, *invp;
    cudaGetSymbolAddress((void**)&xin,  g_xin);
    cudaGetSymbolAddress((void**)&cqkv, g_cqkv);
    cudaGetSymbolAddress((void**)&ckvn, g_ckvn);
    cudaGetSymbolAddress((void**)&kvup, g_kvup);
    cudaGetSymbolAddress((void**)&cqn,  g_cqn);
    cudaGetSymbolAddress((void**)&qf,   g_qf);
    cudaGetSymbolAddress((void**)&Q,    g_Q);
    cudaGetSymbolAddress((void**)&K,    g_K);
    cudaGetSymbolAddress((void**)&V,    g_V);
    cudaGetSymbolAddress((void**)&Ph,   g_Ph);
    cudaGetSymbolAddress((void**)&invp, g_inv);
    cudaGetSymbolAddress((void**)&gg,   g_g);
    cudaGetSymbolAddress((void**)&gp,   g_gp);
    cudaGetSymbolAddress((void**)&ao,   g_ao);
    cudaGetSymbolAddress((void**)&af,   g_af);
    cudaGetSymbolAddress((void**)&x2,   g_x2);
    cudaGetSymbolAddress((void**)&hb,   g_hb);
    cudaGetSymbolAddress((void**)&act,  g_act);
    cudaGetSymbolAddress((void**)&lam,  g_lambda);
    cudaGetSymbolAddress((void**)&wqd_h,  g_wqd_h);
    cudaGetSymbolAddress((void**)&kvuw_h, g_kvuw_h);
    cudaGetSymbolAddress((void**)&quw_h,  g_quw_h);
    cudaGetSymbolAddress((void**)&ow_h,   g_ow_h);
    cudaGetSymbolAddress((void**)&fiw_h,  g_fiw_h);
    cudaGetSymbolAddress((void**)&fow_h,  g_fow_h);

    static bool attr_set = false;
    if (!attr_set) {
        cudaFuncSetAttribute((const void*)hgemm<0,128>, cudaFuncAttributeMaxDynamicSharedMemorySize, SMEM_H128);
        cudaFuncSetAttribute((const void*)hgemm<1,128>, cudaFuncAttributeMaxDynamicSharedMemorySize, SMEM_H128);
        cudaFuncSetAttribute((const void*)hgemm<2,128>, cudaFuncAttributeMaxDynamicSharedMemorySize, SMEM_H128);
        cudaFuncSetAttribute((const void*)hgemm<0,64>,  cudaFuncAttributeMaxDynamicSharedMemorySize, SMEM_H64);
        cudaFuncSetAttribute((const void*)qk_softmax_k, cudaFuncAttributeMaxDynamicSharedMemorySize, QK_SMEM);
        attr_set = true;
    }

    auto grid128 = [](int M, int N, int batch) {
        return dim3((unsigned)(N / 128), (unsigned)(M / 128), (unsigned)batch);
    };
    auto grid64 = [](int M, int N, int batch) {
        return dim3((unsigned)(N / 64), (unsigned)(M / 128), (unsigned)batch);
    };

    // 0. weights -> fp16 in TWO launches. wqd = [kv_down(288) | pad(96) | q_down(384)].
    {
        CvtSeg s0 = { kvdw, wqd_h,               288 * DM };
        CvtSeg s1 = { nullptr, wqd_h + 288 * DM,  96 * DM };   // zero-pad
        CvtSeg s2 = { qdw,  wqd_h + 384 * DM,    QCC * DM };
        CvtSeg s3 = { kvuw, kvuw_h, 2048 * KVCC };
        CvtSeg s4 = { quw,  quw_h,  1536 * QCC };
        CvtSeg s5 = { ow,   ow_h,   DM * DM };
        CvtSeg s6 = { fow,  fow_h,  DM * DFF };
        cvt_all_k<<<2368, 256>>>(s0, s1, s2, s3, s4, s5, s6);
    }
    cvt_swiglu_k<<<4096, 256>>>(fiw, fiw_h);

    // 1. xin = rmsnorm(x) -> fp16
    rmsnorm_h<<<S_LEN, 256>>>(x, n1w, xin, DM, DM, DM, EPS_RMS);
    // 2. cqkv = xin @ [kv_down|q_down]^T  [1536, 768] fp32  (N64: 144 CTAs, one wave)
    hgemm<0,64><<<grid64(S_LEN, 768, 1), 256, SMEM_H64>>>(xin, wqd_h, nullptr, cqkv,
        S_LEN, 768, DM, 0, 0, 0, 1.f);
    // 3. dual rmsnorm: ckvn (cols 0..255) and cqn (cols 384..767)
    rmsnorm_dual_h<<<dim3(S_LEN, 2), 256>>>(cqkv, kvnw, qnw, ckvn, cqn);
    // 4. kvup = ckvn @ kv_up^T [1536, 2048] fp16  (N128: 192 CTAs)
    hgemm<1,128><<<grid128(S_LEN, 2048, 1), 256, SMEM_H128>>>(ckvn, kvuw_h, nullptr, kvup,
        S_LEN, 2048, KVCC, 0, 0, 0, 1.f);
    // 5. qf = cqn @ q_up^T [1536, 1536] fp16  (N128: 144 CTAs)
    hgemm<1,128><<<grid128(S_LEN, 1536, 1), 256, SMEM_H128>>>(cqn, quw_h, nullptr, qf,
        S_LEN, 1536, QCC, 0, 0, 0, 1.f);
    // 6. build Q/K/V (fp16, Q/K padded to 64)
    build_qkv_k<<<S_LEN, 128>>>(qf, kvup, cqkv, fc, fs, Q, K, V);
    // 7. fused QK^T + masked unnormalized softmax
    qk_softmax_k<<<dim3(S_LEN / 128, H2), 256, QK_SMEM>>>(Q, K, Ph, invp);
    // 8. column sums (two-stage deterministic; stage 2 also computes lambda)
    colmean_part_k<<<dim3((S_LEN + 255) / 256, NH, 12), 256>>>(Ph, invp, gp);
    colmean_red_k<<<dim3((S_LEN + 255) / 256, NH), 256>>>(gp, gg, lq1, lk1, lq2, lk2, lam);
    // 9+10. fused combine + AV (K-tile 64)
    av_k<<<dim3(S_LEN / AVM, NH), 256>>>(Ph, invp, V, gg, lam, ao);
    // 11. attn rmsnorm -> fp16 (4 rows per CTA)
    attn_norm_k<<<dim3(S_LEN / 4, NH), 256>>>(ao, anw, af);
    // 12. x2 = x + af @ o_w^T fp32  (N128: 96 CTAs)
    hgemm<0,128><<<grid128(S_LEN, DM, 1), 256, SMEM_H128>>>(af, ow_h, x, x2,
        S_LEN, DM, DM, 0, 0, 0, 1.f);
    // 13. hb = rmsnorm(x2) -> fp16
    rmsnorm_h<<<S_LEN, 256>>>(x2, n2w, hb, DM, DM, DM, EPS_RMS);
    // 14. act = swiglu(hb @ ff_in^T) [1536, 4096] fp16  (N128: 768 CTAs)
    hgemm<2,128><<<grid128(S_LEN, 2 * DFF, 1), 256, SMEM_H128>>>(hb, fiw_h, nullptr, act,
        S_LEN, 2 * DFF, DM, 0, 0, 0, 1.f);
    // 15. out = x2 + act @ ff_out^T fp32  (N128: 96 CTAs)
    hgemm<0,128><<<grid128(S_LEN, DM, 1), 256, SMEM_H128>>>(act, fow_h, x2, outp,
        S_LEN, DM, DFF, 0, 0, 0, 1.f);
}